// round 6
// baseline (speedup 1.0000x reference)
#include <cuda_runtime.h>
#include <cuda_bf16.h>
#include <cstdint>

#define B_ROWS 8192
#define INP    1024
#define HID    1024
#define MEMSZ  256
#define KTOT   2304   // INP + HID + MEMSZ
#define KB2    4608   // bytes per row of fp8 (lo|hi) and bf16-hi rows
#define HM     1280   // HID + MEMSZ
#define A2K    2560   // hi|lo concat for gemm2 A
#define NU     136
#define NUP    144

// ------------------- device scratch (static: no allocation) -------------------
__device__ __align__(16) __nv_bfloat16 g_Ahi[(size_t)B_ROWS * KTOT];  // gemm1 A hi (bf16)
__device__ __align__(16) uint8_t       g_A8 [(size_t)B_ROWS * KB2];   // [lo*512 | hi] e4m3
__device__ __align__(16) __nv_bfloat16 g_Whi[(size_t)HID * KTOT];     // gemm1 W hi (bf16)
__device__ __align__(16) uint8_t       g_W8 [(size_t)HID * KB2];      // [lo*16384 | hi*32] e4m3
__device__ __align__(16) __nv_bfloat16 g_A2bf[(size_t)B_ROWS * A2K];  // gemm2 A hi|lo bf16
__device__ __align__(16) __nv_bfloat16 g_W2bf[(size_t)NUP * A2K];     // gemm2 W hi|lo bf16

// ============================ helpers ============================
__device__ __forceinline__ uint32_t smem_u32(const void* p) {
    uint32_t a;
    asm("{ .reg .u64 t; cvta.to.shared.u64 t, %1; cvt.u32.u64 %0, t; }" : "=r"(a) : "l"(p));
    return a;
}
__device__ __forceinline__ uint32_t swz(uint32_t rowbase128, uint32_t q) {
    return rowbase128 + (q ^ ((rowbase128 >> 3) & 0x70u));
}

#define CP_ASYNC16(saddr, gptr) \
    asm volatile("cp.async.cg.shared.global [%0], [%1], 16;" :: "r"(saddr), "l"(gptr))
#define CP_COMMIT() asm volatile("cp.async.commit_group;" ::: "memory")
#define CP_WAIT1()  asm volatile("cp.async.wait_group 1;" ::: "memory")

__device__ __forceinline__ void ldsm_x4(uint32_t* r, uint32_t addr) {
    asm volatile("ldmatrix.sync.aligned.m8n8.x4.shared.b16 {%0,%1,%2,%3}, [%4];"
                 : "=r"(r[0]), "=r"(r[1]), "=r"(r[2]), "=r"(r[3]) : "r"(addr));
}
__device__ __forceinline__ void ldsm_x2(uint32_t* r, uint32_t addr) {
    asm volatile("ldmatrix.sync.aligned.m8n8.x2.shared.b16 {%0,%1}, [%2];"
                 : "=r"(r[0]), "=r"(r[1]) : "r"(addr));
}
__device__ __forceinline__ void mma16816(float* d, const uint32_t* a,
                                         uint32_t b0, uint32_t b1) {
    asm volatile("mma.sync.aligned.m16n8k16.row.col.f32.bf16.bf16.f32 "
                 "{%0,%1,%2,%3}, {%4,%5,%6,%7}, {%8,%9}, {%0,%1,%2,%3};"
                 : "+f"(d[0]), "+f"(d[1]), "+f"(d[2]), "+f"(d[3])
                 : "r"(a[0]), "r"(a[1]), "r"(a[2]), "r"(a[3]), "r"(b0), "r"(b1));
}
__device__ __forceinline__ void mma_fp8(float* d, const uint32_t* a,
                                        uint32_t b0, uint32_t b1) {
    asm volatile("mma.sync.aligned.m16n8k32.row.col.f32.e4m3.e4m3.f32 "
                 "{%0,%1,%2,%3}, {%4,%5,%6,%7}, {%8,%9}, {%0,%1,%2,%3};"
                 : "+f"(d[0]), "+f"(d[1]), "+f"(d[2]), "+f"(d[3])
                 : "r"(a[0]), "r"(a[1]), "r"(a[2]), "r"(a[3]), "r"(b0), "r"(b1));
}

__device__ __forceinline__ uint32_t pack_e4m3(float k0, float k1, float k2, float k3) {
    uint16_t lo, hi;
    asm("cvt.rn.satfinite.e4m3x2.f32 %0, %1, %2;" : "=h"(lo) : "f"(k1), "f"(k0));
    asm("cvt.rn.satfinite.e4m3x2.f32 %0, %1, %2;" : "=h"(hi) : "f"(k3), "f"(k2));
    return (uint32_t)lo | ((uint32_t)hi << 16);
}

// ============================================================================
// Conversion kernels
// ============================================================================
struct bf4 { __nv_bfloat162 a, b; };

__global__ void convA_kernel(const float* __restrict__ x, const float* __restrict__ h0,
                             const float* __restrict__ mem)
{
    const int gid = blockIdx.x * 256 + threadIdx.x;
    const int row = gid / (KTOT / 4);
    const int k   = (gid % (KTOT / 4)) * 4;
    float4 v;
    if (k < INP)            v = *(const float4*)(x   + (size_t)row * INP + k);
    else if (k < INP + HID) v = *(const float4*)(h0  + (size_t)row * HID + (k - INP));
    else                    v = *(const float4*)(mem + (size_t)row * MEMSZ + (k - INP - HID));

    const __nv_bfloat16 h0b = __float2bfloat16_rn(v.x);
    const __nv_bfloat16 h1b = __float2bfloat16_rn(v.y);
    const __nv_bfloat16 h2b = __float2bfloat16_rn(v.z);
    const __nv_bfloat16 h3b = __float2bfloat16_rn(v.w);
    const float f0 = __bfloat162float(h0b), f1 = __bfloat162float(h1b);
    const float f2 = __bfloat162float(h2b), f3 = __bfloat162float(h3b);
    const float l0 = v.x - f0, l1 = v.y - f1, l2 = v.z - f2, l3 = v.w - f3;

    bf4 hi; hi.a = __nv_bfloat162(h0b, h1b); hi.b = __nv_bfloat162(h2b, h3b);
    *(bf4*)(g_Ahi + (size_t)row * KTOT + k) = hi;

    uint8_t* a8 = g_A8 + (size_t)row * KB2 + k;
    *(uint32_t*)a8          = pack_e4m3(l0 * 512.f, l1 * 512.f, l2 * 512.f, l3 * 512.f);
    *(uint32_t*)(a8 + KTOT) = pack_e4m3(f0, f1, f2, f3);

    if (k >= INP + HID) {   // memory slice also feeds gemm2's A (cols 1024..1280)
        const int km = k - (INP + HID);
        __nv_bfloat16* d = g_A2bf + (size_t)row * A2K + HID + km;
        *(bf4*)d = hi;
        bf4 lo;
        lo.a = __nv_bfloat162(__float2bfloat16_rn(l0), __float2bfloat16_rn(l1));
        lo.b = __nv_bfloat162(__float2bfloat16_rn(l2), __float2bfloat16_rn(l3));
        *(bf4*)(d + HM) = lo;
    }
}

__global__ void convW_kernel(const float* __restrict__ Wh)
{
    const int gid = blockIdx.x * 256 + threadIdx.x;
    const int row = gid / (KTOT / 4);
    const int k   = (gid % (KTOT / 4)) * 4;
    const float4 v = *(const float4*)(Wh + (size_t)row * KTOT + k);

    const __nv_bfloat16 h0b = __float2bfloat16_rn(v.x);
    const __nv_bfloat16 h1b = __float2bfloat16_rn(v.y);
    const __nv_bfloat16 h2b = __float2bfloat16_rn(v.z);
    const __nv_bfloat16 h3b = __float2bfloat16_rn(v.w);
    const float f0 = __bfloat162float(h0b), f1 = __bfloat162float(h1b);
    const float f2 = __bfloat162float(h2b), f3 = __bfloat162float(h3b);
    const float l0 = v.x - f0, l1 = v.y - f1, l2 = v.z - f2, l3 = v.w - f3;

    bf4 hi; hi.a = __nv_bfloat162(h0b, h1b); hi.b = __nv_bfloat162(h2b, h3b);
    *(bf4*)(g_Whi + (size_t)row * KTOT + k) = hi;

    uint8_t* w8 = g_W8 + (size_t)row * KB2 + k;
    *(uint32_t*)w8          = pack_e4m3(l0 * 16384.f, l1 * 16384.f, l2 * 16384.f, l3 * 16384.f);
    *(uint32_t*)(w8 + KTOT) = pack_e4m3(f0 * 32.f, f1 * 32.f, f2 * 32.f, f3 * 32.f);
}

__device__ __forceinline__ const float* u_wrow(int n, const float* Wa, const float* Wb,
                                               const float* Wva, const float* Wvb)
{
    if (n < 4)  return Wa  + (size_t)n * HM;
    if (n < 8)  return Wb  + (size_t)(n - 4) * HM;
    if (n < 72) return Wva + (size_t)(n - 8) * HM;
    return Wvb + (size_t)(n - 72) * HM;
}
__device__ __forceinline__ float u_bias(int n, const float* ba, const float* bb,
                                        const float* bva, const float* bvb)
{
    if (n < 4)  return ba[n];
    if (n < 8)  return bb[n - 4];
    if (n < 72) return bva[n - 8];
    return bvb[n - 72];
}

__global__ void convW2_kernel(const float* __restrict__ Wa, const float* __restrict__ Wb,
                              const float* __restrict__ Wva, const float* __restrict__ Wvb)
{
    const int gid = blockIdx.x * 256 + threadIdx.x;
    if (gid >= NUP * (HM / 4)) return;
    const int n = gid / (HM / 4);
    const int k = (gid % (HM / 4)) * 4;
    float4 v = make_float4(0.f, 0.f, 0.f, 0.f);
    if (n < NU) v = *(const float4*)(u_wrow(n, Wa, Wb, Wva, Wvb) + k);
    const __nv_bfloat16 h0b = __float2bfloat16_rn(v.x);
    const __nv_bfloat16 h1b = __float2bfloat16_rn(v.y);
    const __nv_bfloat16 h2b = __float2bfloat16_rn(v.z);
    const __nv_bfloat16 h3b = __float2bfloat16_rn(v.w);
    bf4 hi, lo;
    hi.a = __nv_bfloat162(h0b, h1b);
    hi.b = __nv_bfloat162(h2b, h3b);
    lo.a = __nv_bfloat162(__float2bfloat16_rn(v.x - __bfloat162float(h0b)),
                          __float2bfloat16_rn(v.y - __bfloat162float(h1b)));
    lo.b = __nv_bfloat162(__float2bfloat16_rn(v.z - __bfloat162float(h2b)),
                          __float2bfloat16_rn(v.w - __bfloat162float(h3b)));
    __nv_bfloat16* dst = g_W2bf + (size_t)n * A2K + k;
    *(bf4*)dst        = hi;
    *(bf4*)(dst + HM) = lo;
}

// ============================================================================
// GEMM1: bf16 hi*hi (mma.m16n8k16) + fp8 cross terms (mma.m16n8k32).
// h = relu(A @ W^T + b). CTA 64x128, 128 threads, 2 CTAs/SM, 2-stage.
// Stage: Ahi(8K) | A8 lo|hi (8K) | Bhi(16K) | B8 lo|hi (16K) = 48KB.
// result = acc_main + acc_cross * 2^-14.
// ============================================================================
#define G1_TM 64
#define G1_TN 128
#define G1_NC 36
#define G1_AHI 0
#define G1_A8  8192
#define G1_BHI 16384
#define G1_B8  32768
#define G1_STG 49152
#define G1_SMEM (2 * G1_STG)

__global__ __launch_bounds__(128, 2)
void gemm1_mma(const float* __restrict__ bh, float* __restrict__ hout)
{
    extern __shared__ __align__(1024) unsigned char smem[];
    const uint32_t sbase = smem_u32(smem);
    const int tid = threadIdx.x;
    const int wid = tid >> 5;
    const int lid = tid & 31;
    const int N0 = blockIdx.x * G1_TN;
    const int M0 = blockIdx.y * G1_TM;

    // ---------- producer addressing (precomputed per r-slot) ----------
    // Ahi: 4 r-slots (512 ops); A8: 4; Bhi: 8; B8: 8. All advance per chunk.
    const char* pAhi[4]; uint32_t sAhi[4];
    const char* pA8[4];  uint32_t sA8[4];
    const char* pBhi[8]; uint32_t sBhi[8];
    const char* pB8[8];  uint32_t sB8[8];
#pragma unroll
    for (int r = 0; r < 4; r++) {
        const int idx = tid + 128 * r, row = idx >> 3, sl = idx & 7;
        pAhi[r] = (const char*)g_Ahi + (size_t)(M0 + row) * (KTOT * 2) + sl * 16;
        sAhi[r] = swz((uint32_t)row * 128, (uint32_t)sl * 16);
        const char* base = (const char*)g_A8 + (size_t)(M0 + row) * KB2;
        pA8[r] = (sl < 4) ? base + sl * 16 : base + KTOT + (sl - 4) * 16;
        sA8[r] = swz((uint32_t)row * 128, (uint32_t)(sl < 4 ? sl * 16 : 64 + (sl - 4) * 16));
    }
#pragma unroll
    for (int r = 0; r < 8; r++) {
        const int idx = tid + 128 * r, row = idx >> 3, sl = idx & 7;
        pBhi[r] = (const char*)g_Whi + (size_t)(N0 + row) * (KTOT * 2) + sl * 16;
        sBhi[r] = swz((uint32_t)row * 128, (uint32_t)sl * 16);
        const char* base = (const char*)g_W8 + (size_t)(N0 + row) * KB2;
        pB8[r] = (sl < 4) ? base + sl * 16 : base + KTOT + (sl - 4) * 16;
        sB8[r] = swz((uint32_t)row * 128, (uint32_t)(sl < 4 ? sl * 16 : 64 + (sl - 4) * 16));
    }

    auto issue_load = [&](int kc, int stage) {
        const uint32_t st = sbase + stage * G1_STG;
        const uint32_t c128 = (uint32_t)kc * 128;
        const uint32_t c64  = (uint32_t)kc * 64;
#pragma unroll
        for (int r = 0; r < 4; r++) {
            CP_ASYNC16(st + G1_AHI + sAhi[r], pAhi[r] + c128);
            CP_ASYNC16(st + G1_A8  + sA8[r],  pA8[r]  + c64);
        }
#pragma unroll
        for (int r = 0; r < 8; r++) {
            CP_ASYNC16(st + G1_BHI + sBhi[r], pBhi[r] + c128);
            CP_ASYNC16(st + G1_B8  + sB8[r],  pB8[r]  + c64);
        }
        CP_COMMIT();
    };

    // ---------- consumer addressing ----------
    const int wm = (wid & 1) * 32;
    const int wn = (wid >> 1) * 64;
    const uint32_t arow128 = (uint32_t)(wm + (lid & 15)) * 128;
    const uint32_t aq      = (uint32_t)((lid >> 4) * 16);
    const uint32_t brow128 = (uint32_t)(wn + (lid & 7) + ((lid >> 4) & 1) * 8) * 128;
    const uint32_t bq      = (uint32_t)(((lid >> 3) & 1) * 16);

    float acc[2][8][4];     // bf16 hi*hi
    float accC[2][8][4];    // fp8 cross, scaled 2^14
#pragma unroll
    for (int i = 0; i < 2; i++)
#pragma unroll
        for (int j = 0; j < 8; j++)
#pragma unroll
            for (int q = 0; q < 4; q++) { acc[i][j][q] = 0.f; accC[i][j][q] = 0.f; }

    issue_load(0, 0);
    issue_load(1, 1);

#pragma unroll 1
    for (int kc = 0; kc < G1_NC; kc++) {
        CP_WAIT1();
        __syncthreads();
        const uint32_t st = sbase + (kc & 1) * G1_STG;

        // ---- bf16 hi*hi: 4 k16 steps ----
#pragma unroll
        for (int kk = 0; kk < 4; kk++) {
            const uint32_t kb = (uint32_t)kk * 32;
            uint32_t Ah[2][4], Bh[4][4];
#pragma unroll
            for (int mt = 0; mt < 2; mt++)
                ldsm_x4(Ah[mt], st + G1_AHI + swz(arow128 + mt * 16 * 128, kb + aq));
#pragma unroll
            for (int nt = 0; nt < 4; nt++)
                ldsm_x4(Bh[nt], st + G1_BHI + swz(brow128 + nt * 16 * 128, kb + bq));
#pragma unroll
            for (int mt = 0; mt < 2; mt++)
#pragma unroll
                for (int nt = 0; nt < 4; nt++) {
                    mma16816(acc[mt][2 * nt],     Ah[mt], Bh[nt][0], Bh[nt][1]);
                    mma16816(acc[mt][2 * nt + 1], Ah[mt], Bh[nt][2], Bh[nt][3]);
                }
        }

        // ---- fp8 cross terms: 2 k32 steps ----
#pragma unroll
        for (int s = 0; s < 2; s++) {
            const uint32_t ks = (uint32_t)s * 32;
            uint32_t Alo[2][4], Ahi8[2][4], Blo[4][4], Bhi8[4][4];
#pragma unroll
            for (int mt = 0; mt < 2; mt++) {
                ldsm_x4(Alo[mt],  st + G1_A8 + swz(arow128 + mt * 16 * 128, ks + aq));
                ldsm_x4(Ahi8[mt], st + G1_A8 + swz(arow128 + mt * 16 * 128, 64 + ks + aq));
            }
#pragma unroll
            for (int nt = 0; nt < 4; nt++) {
                ldsm_x4(Blo[nt],  st + G1_B8 + swz(brow128 + nt * 16 * 128, ks + bq));
                ldsm_x4(Bhi8[nt], st + G1_B8 + swz(brow128 + nt * 16 * 128, 64 + ks + bq));
            }
#pragma unroll
            for (int mt = 0; mt < 2; mt++)
#pragma unroll
                for (int nt = 0; nt < 4; nt++) {
                    // a_lo(2^9) * b_hi(2^5) -> 2^14
                    mma_fp8(accC[mt][2 * nt],     Alo[mt],  Bhi8[nt][0], Bhi8[nt][1]);
                    mma_fp8(accC[mt][2 * nt + 1], Alo[mt],  Bhi8[nt][2], Bhi8[nt][3]);
                    // a_hi(2^0) * b_lo(2^14) -> 2^14
                    mma_fp8(accC[mt][2 * nt],     Ahi8[mt], Blo[nt][0], Blo[nt][1]);
                    mma_fp8(accC[mt][2 * nt + 1], Ahi8[mt], Blo[nt][2], Blo[nt][3]);
                }
        }

        __syncthreads();
        if (kc + 2 < G1_NC) issue_load(kc + 2, kc & 1);
        else CP_COMMIT();
    }

    // ---------- epilogue ----------
    const float CS = 1.f / 16384.f;
#pragma unroll
    for (int mt = 0; mt < 2; mt++) {
        const int m = M0 + wm + mt * 16 + (lid >> 2);
#pragma unroll
        for (int nt = 0; nt < 8; nt++) {
            const int n = N0 + wn + nt * 8 + (lid & 3) * 2;
            const float2 bv = *(const float2*)(bh + n);
            float2 v0, v1;
            v0.x = acc[mt][nt][0] + accC[mt][nt][0] * CS + bv.x;
            v0.y = acc[mt][nt][1] + accC[mt][nt][1] * CS + bv.y;
            v1.x = acc[mt][nt][2] + accC[mt][nt][2] * CS + bv.x;
            v1.y = acc[mt][nt][3] + accC[mt][nt][3] * CS + bv.y;
            v0.x = v0.x > 0.f ? v0.x : 0.f; v0.y = v0.y > 0.f ? v0.y : 0.f;
            v1.x = v1.x > 0.f ? v1.x : 0.f; v1.y = v1.y > 0.f ? v1.y : 0.f;
            *(float2*)(hout + (size_t)m * HID + n)       = v0;
            *(float2*)(hout + (size_t)(m + 8) * HID + n) = v1;

            const __nv_bfloat16 h00 = __float2bfloat16_rn(v0.x);
            const __nv_bfloat16 h01 = __float2bfloat16_rn(v0.y);
            const __nv_bfloat16 h10 = __float2bfloat16_rn(v1.x);
            const __nv_bfloat16 h11 = __float2bfloat16_rn(v1.y);
            __nv_bfloat16* d0 = g_A2bf + (size_t)m * A2K + n;
            __nv_bfloat16* d1 = g_A2bf + (size_t)(m + 8) * A2K + n;
            *(__nv_bfloat162*)d0 = __nv_bfloat162(h00, h01);
            *(__nv_bfloat162*)d1 = __nv_bfloat162(h10, h11);
            *(__nv_bfloat162*)(d0 + HM) =
                __nv_bfloat162(__float2bfloat16_rn(v0.x - __bfloat162float(h00)),
                               __float2bfloat16_rn(v0.y - __bfloat162float(h01)));
            *(__nv_bfloat162*)(d1 + HM) =
                __nv_bfloat162(__float2bfloat16_rn(v1.x - __bfloat162float(h10)),
                               __float2bfloat16_rn(v1.y - __bfloat162float(h11)));
        }
    }
}

// ============================================================================
// GEMM2 via mma.sync + fused finish (unchanged).
// ============================================================================
#define NSTAGE 3
#define G2_TM 64
#define G2_NCHUNK 60
#define G2_SA (G2_TM * 128)
#define G2_SB (NUP * 128)
#define G2_STG (G2_SA + G2_SB)
#define G2_SMEM (3 * G2_STG)

__global__ __launch_bounds__(256, 1)
void gemm2_mma(const float* __restrict__ mem,
               const float* __restrict__ ba, const float* __restrict__ bb,
               const float* __restrict__ bva, const float* __restrict__ bvb,
               float* __restrict__ mem_new)
{
    extern __shared__ __align__(1024) unsigned char smem[];
    const uint32_t sbase = smem_u32(smem);
    const int tid = threadIdx.x;
    const int wid = tid >> 5;
    const int lid = tid & 31;
    const int M0 = blockIdx.x * G2_TM;

    const int prow = tid >> 3;
    const int pc   = tid & 7;
    const char* Ag = (const char*)g_A2bf + (size_t)(M0 + prow) * (A2K * 2) + pc * 16;
    const uint32_t sAoff = swz((uint32_t)prow * 128, (uint32_t)pc * 16);

    auto issue_load = [&](int kc, int stage) {
        uint32_t aoff, boff;
        if (kc < 20)      { aoff = kc * 128;               boff = kc * 128; }
        else if (kc < 40) { aoff = 2560 + (kc - 20) * 128; boff = (kc - 20) * 128; }
        else              { aoff = (kc - 40) * 128;        boff = 2560 + (kc - 40) * 128; }
        const uint32_t sa  = sbase + stage * G2_STG;
        const uint32_t sbB = sa + G2_SA;
#pragma unroll
        for (int r = 0; r < 2; r++)
            CP_ASYNC16(sa + sAoff + r * 4096, Ag + aoff + (size_t)r * (32 * A2K * 2));
#pragma unroll
        for (int r = 0; r < 5; r++) {
            const int idx = tid + 256 * r;
            if (idx < NUP * 8) {
                const int row = idx >> 3, c = idx & 7;
                CP_ASYNC16(sbB + swz((uint32_t)row * 128, (uint32_t)c * 16),
                           (const char*)g_W2bf + (size_t)row * (A2K * 2) + c * 16 + boff);
            }
        }
        CP_COMMIT();
    };

    const int wm = (wid & 3) * 16;
    const int wn = (wid >> 2) * 72;
    const uint32_t arow128 = (uint32_t)(wm + (lid & 15)) * 128;
    const uint32_t aq      = (uint32_t)((lid >> 4) * 16);
    const uint32_t brow128 = (uint32_t)((lid & 7) + ((lid >> 4) & 1) * 8) * 128;
    const uint32_t bq      = (uint32_t)(((lid >> 3) & 1) * 16);
    const uint32_t brow2   = (uint32_t)(lid & 7) * 128;

    float acc[9][4];
#pragma unroll
    for (int j = 0; j < 9; j++)
#pragma unroll
        for (int q = 0; q < 4; q++) acc[j][q] = 0.f;

    issue_load(0, 0);
    issue_load(1, 1);

#pragma unroll 1
    for (int kc = 0; kc < G2_NCHUNK; kc++) {
        CP_WAIT1();
        __syncthreads();
        if (kc + 2 < G2_NCHUNK) issue_load(kc + 2, (kc + 2) % NSTAGE);
        else CP_COMMIT();

        const uint32_t sa  = sbase + (kc % NSTAGE) * G2_STG;
        const uint32_t sbB = sa + G2_SA;
#pragma unroll
        for (int kk = 0; kk < 4; kk++) {
            const uint32_t kb = (uint32_t)kk * 32;
            uint32_t A[4];
            ldsm_x4(A, sa + swz(arow128, kb + aq));
            uint32_t Bf[4][4], Bt[2];
#pragma unroll
            for (int nt = 0; nt < 4; nt++)
                ldsm_x4(Bf[nt], sbB + swz(brow128 + (wn + nt * 16) * 128, kb + bq));
            ldsm_x2(Bt, sbB + swz(brow2 + (wn + 64) * 128, kb + bq));
#pragma unroll
            for (int nt = 0; nt < 4; nt++) {
                mma16816(acc[2 * nt],     A, Bf[nt][0], Bf[nt][1]);
                mma16816(acc[2 * nt + 1], A, Bf[nt][2], Bf[nt][3]);
            }
            mma16816(acc[8], A, Bt[0], Bt[1]);
        }
    }

    __syncthreads();
    float* su = (float*)smem;                      // [64][144]
    float* Pa = (float*)(smem + 64 * NUP * 4);     // [64][8]
    float* Pb = Pa + 64 * 8;
    {
        const int r0 = wm + (lid >> 2);
        const int r1 = r0 + 8;
#pragma unroll
        for (int nt = 0; nt < 9; nt++) {
            const int n = wn + nt * 8 + (lid & 3) * 2;
            float b0 = 0.f, b1 = 0.f;
            if (n < NU)     b0 = u_bias(n,     ba, bb, bva, bvb);
            if (n + 1 < NU) b1 = u_bias(n + 1, ba, bb, bva, bvb);
            su[r0 * NUP + n]     = acc[nt][0] + b0;
            su[r0 * NUP + n + 1] = acc[nt][1] + b1;
            su[r1 * NUP + n]     = acc[nt][2] + b0;
            su[r1 * NUP + n + 1] = acc[nt][3] + b1;
        }
    }
    __syncthreads();

    if (tid < 64) {
        const float* u   = su + tid * NUP;
        const float* al  = u;
        const float* be  = u + 4;
        const float* u0a = u + 8;
        const float* u1a = u + 40;
        const float* u0b = u + 72;
        const float* u1b = u + 104;

        float S1a = 0.f, S1b = 0.f;
#pragma unroll
        for (int j = 0; j < 32; j++) {
            const float xa = u1a[j], xa2 = xa * xa;
            const float xb = u1b[j], xb2 = xb * xb;
            S1a += xa2 * xa2 * fabsf(xa);
            S1b += xb2 * xb2 * fabsf(xb);
        }
        float ca[4], cb[4];
#pragma unroll
        for (int k = 0; k < 4; k++) {
            float S0a = 0.f, S0b = 0.f;
#pragma unroll
            for (int i = 0; i < 8; i++) {
                const float xa = u0a[8 * k + i], xa2 = xa * xa;
                const float xb = u0b[8 * k + i], xb2 = xb * xb;
                S0a += xa2 * xa2 * fabsf(xa);
                S0b += xb2 * xb2 * fabsf(xb);
            }
            const float na = fmaxf(exp2f(0.2f * log2f(S0a * S1a)), 1e-12f);
            const float nb = fmaxf(exp2f(0.2f * log2f(S0b * S1b)), 1e-12f);
            ca[k] = al[k] / na;
            cb[k] = be[k] / nb;
        }
#pragma unroll
        for (int ii = 0; ii < 8; ii++) {
            float pa = 0.f, pb = 0.f;
#pragma unroll
            for (int k = 0; k < 4; k++) {
                pa += ca[k] * u0a[8 * k + ii];
                pb += cb[k] * u0b[8 * k + ii];
            }
            Pa[tid * 8 + ii] = pa;
            Pb[tid * 8 + ii] = pb;
        }
    }
    __syncthreads();

#pragma unroll
    for (int e = 0; e < 64; e++) {
        const int idx = tid + e * 256;
        const int m = idx >> 8;
        const int c = idx & 255;
        const int ii = c >> 5;
        const int j  = c & 31;
        const float* u = su + m * NUP;
        mem_new[(size_t)(M0 + m) * MEMSZ + c] =
            mem[(size_t)(M0 + m) * MEMSZ + c] +
            0.25f * (u[40 + j] * Pa[m * 8 + ii] - u[104 + j] * Pb[m * 8 + ii]);
    }
}

// ============================================================================
// Launch
// ============================================================================
extern "C" void kernel_launch(void* const* d_in, const int* in_sizes, int n_in,
                              void* d_out, int out_size)
{
    const float* x   = (const float*)d_in[0];
    const float* h0  = (const float*)d_in[1];
    const float* mem = (const float*)d_in[2];
    const float* Wh  = (const float*)d_in[3];
    const float* bh  = (const float*)d_in[4];
    const float* Wa  = (const float*)d_in[5];
    const float* ba  = (const float*)d_in[6];
    const float* Wb  = (const float*)d_in[7];
    const float* bb  = (const float*)d_in[8];
    const float* Wva = (const float*)d_in[9];
    const float* bva = (const float*)d_in[10];
    const float* Wvb = (const float*)d_in[11];
    const float* bvb = (const float*)d_in[12];

    float* out     = (float*)d_out;
    float* mem_new = out;                              // [B, 256]
    float* h       = out + (size_t)B_ROWS * MEMSZ;     // [B, 1024]

    cudaFuncSetAttribute(gemm1_mma, cudaFuncAttributeMaxDynamicSharedMemorySize, G1_SMEM);
    cudaFuncSetAttribute(gemm2_mma, cudaFuncAttributeMaxDynamicSharedMemorySize, G2_SMEM);

    convA_kernel<<<(B_ROWS * (KTOT / 4)) / 256, 256>>>(x, h0, mem);
    convW_kernel<<<(HID * (KTOT / 4)) / 256, 256>>>(Wh);
    convW2_kernel<<<(NUP * (HM / 4) + 255) / 256, 256>>>(Wa, Wb, Wva, Wvb);
    gemm1_mma<<<dim3(HID / G1_TN, B_ROWS / G1_TM), 128, G1_SMEM>>>(bh, h);
    gemm2_mma<<<B_ROWS / G2_TM, 256, G2_SMEM>>>(mem, ba, bb, bva, bvb, mem_new);
}

// round 7
// speedup vs baseline: 1.5934x; 1.5934x over previous
#include <cuda_runtime.h>
#include <cuda_bf16.h>
#include <cuda_fp16.h>
#include <cstdint>

#define B_ROWS 8192
#define INP    1024
#define HID    1024
#define MEMSZ  256
#define KTOT   2304   // INP + HID + MEMSZ
#define HM     1280   // HID + MEMSZ
#define A2K    2560   // hi|lo concat for gemm2 A
#define NU     136
#define NUP    144

// ------------------- device scratch (static: no allocation) -------------------
__device__ __align__(16) __half        g_A16[(size_t)B_ROWS * KTOT];   // gemm1 A fp16
__device__ __align__(16) __half        g_W16[(size_t)HID * (2 * KTOT)];// gemm1 W*2^10 hi|lo fp16
__device__ __align__(16) __nv_bfloat16 g_A2bf[(size_t)B_ROWS * A2K];   // gemm2 A hi|lo bf16
__device__ __align__(16) __nv_bfloat16 g_W2bf[(size_t)NUP * A2K];      // gemm2 W hi|lo bf16

// ============================ helpers ============================
__device__ __forceinline__ uint32_t smem_u32(const void* p) {
    uint32_t a;
    asm("{ .reg .u64 t; cvta.to.shared.u64 t, %1; cvt.u32.u64 %0, t; }" : "=r"(a) : "l"(p));
    return a;
}
__device__ __forceinline__ uint32_t swz(uint32_t rowbase128, uint32_t q) {
    return rowbase128 + (q ^ ((rowbase128 >> 3) & 0x70u));
}

#define CP_ASYNC16(saddr, gptr) \
    asm volatile("cp.async.cg.shared.global [%0], [%1], 16;" :: "r"(saddr), "l"(gptr))
#define CP_COMMIT() asm volatile("cp.async.commit_group;" ::: "memory")
#define CP_WAIT1()  asm volatile("cp.async.wait_group 1;" ::: "memory")

__device__ __forceinline__ void ldsm_x4(uint32_t* r, uint32_t addr) {
    asm volatile("ldmatrix.sync.aligned.m8n8.x4.shared.b16 {%0,%1,%2,%3}, [%4];"
                 : "=r"(r[0]), "=r"(r[1]), "=r"(r[2]), "=r"(r[3]) : "r"(addr));
}
__device__ __forceinline__ void ldsm_x2(uint32_t* r, uint32_t addr) {
    asm volatile("ldmatrix.sync.aligned.m8n8.x2.shared.b16 {%0,%1}, [%2];"
                 : "=r"(r[0]), "=r"(r[1]) : "r"(addr));
}
__device__ __forceinline__ void mma16816(float* d, const uint32_t* a,
                                         uint32_t b0, uint32_t b1) {
    asm volatile("mma.sync.aligned.m16n8k16.row.col.f32.bf16.bf16.f32 "
                 "{%0,%1,%2,%3}, {%4,%5,%6,%7}, {%8,%9}, {%0,%1,%2,%3};"
                 : "+f"(d[0]), "+f"(d[1]), "+f"(d[2]), "+f"(d[3])
                 : "r"(a[0]), "r"(a[1]), "r"(a[2]), "r"(a[3]), "r"(b0), "r"(b1));
}
__device__ __forceinline__ void mma_f16(float* d, const uint32_t* a,
                                        uint32_t b0, uint32_t b1) {
    asm volatile("mma.sync.aligned.m16n8k16.row.col.f32.f16.f16.f32 "
                 "{%0,%1,%2,%3}, {%4,%5,%6,%7}, {%8,%9}, {%0,%1,%2,%3};"
                 : "+f"(d[0]), "+f"(d[1]), "+f"(d[2]), "+f"(d[3])
                 : "r"(a[0]), "r"(a[1]), "r"(a[2]), "r"(a[3]), "r"(b0), "r"(b1));
}

// ============================================================================
// Conversion kernels
// ============================================================================
struct bf4 { __nv_bfloat162 a, b; };
struct hf4 { __half2 a, b; };

__global__ void convA_kernel(const float* __restrict__ x, const float* __restrict__ h0,
                             const float* __restrict__ mem)
{
    const int gid = blockIdx.x * 256 + threadIdx.x;
    const int row = gid / (KTOT / 4);
    const int k   = (gid % (KTOT / 4)) * 4;
    float4 v;
    if (k < INP)            v = *(const float4*)(x   + (size_t)row * INP + k);
    else if (k < INP + HID) v = *(const float4*)(h0  + (size_t)row * HID + (k - INP));
    else                    v = *(const float4*)(mem + (size_t)row * MEMSZ + (k - INP - HID));

    hf4 a16;
    a16.a = __half2(__float2half_rn(v.x), __float2half_rn(v.y));
    a16.b = __half2(__float2half_rn(v.z), __float2half_rn(v.w));
    *(hf4*)(g_A16 + (size_t)row * KTOT + k) = a16;

    if (k >= INP + HID) {   // memory slice also feeds gemm2's A (cols 1024..1280)
        const int km = k - (INP + HID);
        const __nv_bfloat16 h0b = __float2bfloat16_rn(v.x);
        const __nv_bfloat16 h1b = __float2bfloat16_rn(v.y);
        const __nv_bfloat16 h2b = __float2bfloat16_rn(v.z);
        const __nv_bfloat16 h3b = __float2bfloat16_rn(v.w);
        bf4 hi, lo;
        hi.a = __nv_bfloat162(h0b, h1b);
        hi.b = __nv_bfloat162(h2b, h3b);
        lo.a = __nv_bfloat162(__float2bfloat16_rn(v.x - __bfloat162float(h0b)),
                              __float2bfloat16_rn(v.y - __bfloat162float(h1b)));
        lo.b = __nv_bfloat162(__float2bfloat16_rn(v.z - __bfloat162float(h2b)),
                              __float2bfloat16_rn(v.w - __bfloat162float(h3b)));
        __nv_bfloat16* d = g_A2bf + (size_t)row * A2K + HID + km;
        *(bf4*)d        = hi;
        *(bf4*)(d + HM) = lo;
    }
}

// W*2^10 -> fp16 hi + fp16 lo (lo exact residual, both normal-range)
__global__ void convW_kernel(const float* __restrict__ Wh)
{
    const int gid = blockIdx.x * 256 + threadIdx.x;
    const int row = gid / (KTOT / 4);
    const int k   = (gid % (KTOT / 4)) * 4;
    const float4 v = *(const float4*)(Wh + (size_t)row * KTOT + k);
    const float s0 = v.x * 1024.f, s1 = v.y * 1024.f;
    const float s2 = v.z * 1024.f, s3 = v.w * 1024.f;
    const __half h0 = __float2half_rn(s0);
    const __half h1 = __float2half_rn(s1);
    const __half h2 = __float2half_rn(s2);
    const __half h3 = __float2half_rn(s3);
    hf4 hi, lo;
    hi.a = __half2(h0, h1); hi.b = __half2(h2, h3);
    lo.a = __half2(__float2half_rn(s0 - __half2float(h0)),
                   __float2half_rn(s1 - __half2float(h1)));
    lo.b = __half2(__float2half_rn(s2 - __half2float(h2)),
                   __float2half_rn(s3 - __half2float(h3)));
    __half* dst = g_W16 + (size_t)row * (2 * KTOT) + k;
    *(hf4*)dst          = hi;
    *(hf4*)(dst + KTOT) = lo;
}

__device__ __forceinline__ const float* u_wrow(int n, const float* Wa, const float* Wb,
                                               const float* Wva, const float* Wvb)
{
    if (n < 4)  return Wa  + (size_t)n * HM;
    if (n < 8)  return Wb  + (size_t)(n - 4) * HM;
    if (n < 72) return Wva + (size_t)(n - 8) * HM;
    return Wvb + (size_t)(n - 72) * HM;
}
__device__ __forceinline__ float u_bias(int n, const float* ba, const float* bb,
                                        const float* bva, const float* bvb)
{
    if (n < 4)  return ba[n];
    if (n < 8)  return bb[n - 4];
    if (n < 72) return bva[n - 8];
    return bvb[n - 72];
}

__global__ void convW2_kernel(const float* __restrict__ Wa, const float* __restrict__ Wb,
                              const float* __restrict__ Wva, const float* __restrict__ Wvb)
{
    const int gid = blockIdx.x * 256 + threadIdx.x;
    if (gid >= NUP * (HM / 4)) return;
    const int n = gid / (HM / 4);
    const int k = (gid % (HM / 4)) * 4;
    float4 v = make_float4(0.f, 0.f, 0.f, 0.f);
    if (n < NU) v = *(const float4*)(u_wrow(n, Wa, Wb, Wva, Wvb) + k);
    const __nv_bfloat16 h0b = __float2bfloat16_rn(v.x);
    const __nv_bfloat16 h1b = __float2bfloat16_rn(v.y);
    const __nv_bfloat16 h2b = __float2bfloat16_rn(v.z);
    const __nv_bfloat16 h3b = __float2bfloat16_rn(v.w);
    bf4 hi, lo;
    hi.a = __nv_bfloat162(h0b, h1b);
    hi.b = __nv_bfloat162(h2b, h3b);
    lo.a = __nv_bfloat162(__float2bfloat16_rn(v.x - __bfloat162float(h0b)),
                          __float2bfloat16_rn(v.y - __bfloat162float(h1b)));
    lo.b = __nv_bfloat162(__float2bfloat16_rn(v.z - __bfloat162float(h2b)),
                          __float2bfloat16_rn(v.w - __bfloat162float(h3b)));
    __nv_bfloat16* dst = g_W2bf + (size_t)n * A2K + k;
    *(bf4*)dst        = hi;
    *(bf4*)(dst + HM) = lo;
}

// ============================================================================
// GEMM1: fp16 2-product split, single fp32 accumulator.
// h = relu((A16 @ (Whi + Wlo)^T) * 2^-10 + b).
// CTA 64x128, 128 threads (4 warps, 2Mx2N), 2 CTAs/SM, 2-stage pipeline.
// Stage: A(8K) | Bhi(16K) | Blo(16K) = 40KB.
// ============================================================================
#define G1_TM 64
#define G1_TN 128
#define G1_NC 36
#define G1_A   0
#define G1_BHI 8192
#define G1_BLO 24576
#define G1_STG 40960
#define G1_SMEM (2 * G1_STG)   // 81920

__global__ __launch_bounds__(128, 2)
void gemm1_mma(const float* __restrict__ bh, float* __restrict__ hout)
{
    extern __shared__ __align__(1024) unsigned char smem[];
    const uint32_t sbase = smem_u32(smem);
    const int tid = threadIdx.x;
    const int wid = tid >> 5;
    const int lid = tid & 31;
    const int N0 = blockIdx.x * G1_TN;
    const int M0 = blockIdx.y * G1_TM;

    // ---------- producer addressing ----------
    const char* pA[4];  uint32_t sA[4];
    const char* pB[8];  uint32_t sB[8];
#pragma unroll
    for (int r = 0; r < 4; r++) {
        const int idx = tid + 128 * r, row = idx >> 3, sl = idx & 7;
        pA[r] = (const char*)g_A16 + (size_t)(M0 + row) * (KTOT * 2) + sl * 16;
        sA[r] = swz((uint32_t)row * 128, (uint32_t)sl * 16);
    }
#pragma unroll
    for (int r = 0; r < 8; r++) {
        const int idx = tid + 128 * r, row = idx >> 3, sl = idx & 7;
        pB[r] = (const char*)g_W16 + (size_t)(N0 + row) * (KTOT * 4) + sl * 16;
        sB[r] = swz((uint32_t)row * 128, (uint32_t)sl * 16);
    }

    auto issue_load = [&](int kc, int stage) {
        const uint32_t st = sbase + stage * G1_STG;
        const uint32_t cb = (uint32_t)kc * 128;
#pragma unroll
        for (int r = 0; r < 4; r++)
            CP_ASYNC16(st + G1_A + sA[r], pA[r] + cb);
#pragma unroll
        for (int r = 0; r < 8; r++) {
            CP_ASYNC16(st + G1_BHI + sB[r], pB[r] + cb);
            CP_ASYNC16(st + G1_BLO + sB[r], pB[r] + cb + KTOT * 2);
        }
        CP_COMMIT();
    };

    // ---------- consumer addressing ----------
    const int wm = (wid & 1) * 32;
    const int wn = (wid >> 1) * 64;
    const uint32_t arow128 = (uint32_t)(wm + (lid & 15)) * 128;
    const uint32_t aq      = (uint32_t)((lid >> 4) * 16);
    const uint32_t brow128 = (uint32_t)(wn + (lid & 7) + ((lid >> 4) & 1) * 8) * 128;
    const uint32_t bq      = (uint32_t)(((lid >> 3) & 1) * 16);

    float acc[2][8][4];
#pragma unroll
    for (int i = 0; i < 2; i++)
#pragma unroll
        for (int j = 0; j < 8; j++)
#pragma unroll
            for (int q = 0; q < 4; q++) acc[i][j][q] = 0.f;

    issue_load(0, 0);
    issue_load(1, 1);

#pragma unroll 1
    for (int kc = 0; kc < G1_NC; kc++) {
        CP_WAIT1();
        __syncthreads();
        const uint32_t st = sbase + (kc & 1) * G1_STG;
#pragma unroll
        for (int kk = 0; kk < 4; kk++) {
            const uint32_t kb = (uint32_t)kk * 32;
            uint32_t A[2][4], Bh[4][4], Bl[4][4];
#pragma unroll
            for (int mt = 0; mt < 2; mt++)
                ldsm_x4(A[mt], st + G1_A + swz(arow128 + mt * 16 * 128, kb + aq));
#pragma unroll
            for (int nt = 0; nt < 4; nt++) {
                ldsm_x4(Bh[nt], st + G1_BHI + swz(brow128 + nt * 16 * 128, kb + bq));
                ldsm_x4(Bl[nt], st + G1_BLO + swz(brow128 + nt * 16 * 128, kb + bq));
            }
#pragma unroll
            for (int mt = 0; mt < 2; mt++)
#pragma unroll
                for (int nt = 0; nt < 4; nt++) {
                    mma_f16(acc[mt][2 * nt],     A[mt], Bh[nt][0], Bh[nt][1]);
                    mma_f16(acc[mt][2 * nt + 1], A[mt], Bh[nt][2], Bh[nt][3]);
                    mma_f16(acc[mt][2 * nt],     A[mt], Bl[nt][0], Bl[nt][1]);
                    mma_f16(acc[mt][2 * nt + 1], A[mt], Bl[nt][2], Bl[nt][3]);
                }
        }
        __syncthreads();
        if (kc + 2 < G1_NC) issue_load(kc + 2, kc & 1);
        else CP_COMMIT();
    }

    // ---------- epilogue: scale 2^-10, bias, relu; fp32 h + bf16 hi/lo ----------
    const float WS = 1.f / 1024.f;
#pragma unroll
    for (int mt = 0; mt < 2; mt++) {
        const int m = M0 + wm + mt * 16 + (lid >> 2);
#pragma unroll
        for (int nt = 0; nt < 8; nt++) {
            const int n = N0 + wn + nt * 8 + (lid & 3) * 2;
            const float2 bv = *(const float2*)(bh + n);
            float2 v0, v1;
            v0.x = acc[mt][nt][0] * WS + bv.x; v0.y = acc[mt][nt][1] * WS + bv.y;
            v1.x = acc[mt][nt][2] * WS + bv.x; v1.y = acc[mt][nt][3] * WS + bv.y;
            v0.x = v0.x > 0.f ? v0.x : 0.f; v0.y = v0.y > 0.f ? v0.y : 0.f;
            v1.x = v1.x > 0.f ? v1.x : 0.f; v1.y = v1.y > 0.f ? v1.y : 0.f;
            *(float2*)(hout + (size_t)m * HID + n)       = v0;
            *(float2*)(hout + (size_t)(m + 8) * HID + n) = v1;

            const __nv_bfloat16 h00 = __float2bfloat16_rn(v0.x);
            const __nv_bfloat16 h01 = __float2bfloat16_rn(v0.y);
            const __nv_bfloat16 h10 = __float2bfloat16_rn(v1.x);
            const __nv_bfloat16 h11 = __float2bfloat16_rn(v1.y);
            __nv_bfloat16* d0 = g_A2bf + (size_t)m * A2K + n;
            __nv_bfloat16* d1 = g_A2bf + (size_t)(m + 8) * A2K + n;
            *(__nv_bfloat162*)d0 = __nv_bfloat162(h00, h01);
            *(__nv_bfloat162*)d1 = __nv_bfloat162(h10, h11);
            *(__nv_bfloat162*)(d0 + HM) =
                __nv_bfloat162(__float2bfloat16_rn(v0.x - __bfloat162float(h00)),
                               __float2bfloat16_rn(v0.y - __bfloat162float(h01)));
            *(__nv_bfloat162*)(d1 + HM) =
                __nv_bfloat162(__float2bfloat16_rn(v1.x - __bfloat162float(h10)),
                               __float2bfloat16_rn(v1.y - __bfloat162float(h11)));
        }
    }
}

// ============================================================================
// GEMM2 via mma.sync + fused finish (proven round-5 version, unchanged).
// ============================================================================
#define NSTAGE 3
#define G2_TM 64
#define G2_NCHUNK 60
#define G2_SA (G2_TM * 128)
#define G2_SB (NUP * 128)
#define G2_STG (G2_SA + G2_SB)
#define G2_SMEM (3 * G2_STG)

__global__ __launch_bounds__(256, 1)
void gemm2_mma(const float* __restrict__ mem,
               const float* __restrict__ ba, const float* __restrict__ bb,
               const float* __restrict__ bva, const float* __restrict__ bvb,
               float* __restrict__ mem_new)
{
    extern __shared__ __align__(1024) unsigned char smem[];
    const uint32_t sbase = smem_u32(smem);
    const int tid = threadIdx.x;
    const int wid = tid >> 5;
    const int lid = tid & 31;
    const int M0 = blockIdx.x * G2_TM;

    const int prow = tid >> 3;
    const int pc   = tid & 7;
    const char* Ag = (const char*)g_A2bf + (size_t)(M0 + prow) * (A2K * 2) + pc * 16;
    const uint32_t sAoff = swz((uint32_t)prow * 128, (uint32_t)pc * 16);

    auto issue_load = [&](int kc, int stage) {
        uint32_t aoff, boff;
        if (kc < 20)      { aoff = kc * 128;               boff = kc * 128; }
        else if (kc < 40) { aoff = 2560 + (kc - 20) * 128; boff = (kc - 20) * 128; }
        else              { aoff = (kc - 40) * 128;        boff = 2560 + (kc - 40) * 128; }
        const uint32_t sa  = sbase + stage * G2_STG;
        const uint32_t sbB = sa + G2_SA;
#pragma unroll
        for (int r = 0; r < 2; r++)
            CP_ASYNC16(sa + sAoff + r * 4096, Ag + aoff + (size_t)r * (32 * A2K * 2));
#pragma unroll
        for (int r = 0; r < 5; r++) {
            const int idx = tid + 256 * r;
            if (idx < NUP * 8) {
                const int row = idx >> 3, c = idx & 7;
                CP_ASYNC16(sbB + swz((uint32_t)row * 128, (uint32_t)c * 16),
                           (const char*)g_W2bf + (size_t)row * (A2K * 2) + c * 16 + boff);
            }
        }
        CP_COMMIT();
    };

    const int wm = (wid & 3) * 16;
    const int wn = (wid >> 2) * 72;
    const uint32_t arow128 = (uint32_t)(wm + (lid & 15)) * 128;
    const uint32_t aq      = (uint32_t)((lid >> 4) * 16);
    const uint32_t brow128 = (uint32_t)((lid & 7) + ((lid >> 4) & 1) * 8) * 128;
    const uint32_t bq      = (uint32_t)(((lid >> 3) & 1) * 16);
    const uint32_t brow2   = (uint32_t)(lid & 7) * 128;

    float acc[9][4];
#pragma unroll
    for (int j = 0; j < 9; j++)
#pragma unroll
        for (int q = 0; q < 4; q++) acc[j][q] = 0.f;

    issue_load(0, 0);
    issue_load(1, 1);

#pragma unroll 1
    for (int kc = 0; kc < G2_NCHUNK; kc++) {
        CP_WAIT1();
        __syncthreads();
        if (kc + 2 < G2_NCHUNK) issue_load(kc + 2, (kc + 2) % NSTAGE);
        else CP_COMMIT();

        const uint32_t sa  = sbase + (kc % NSTAGE) * G2_STG;
        const uint32_t sbB = sa + G2_SA;
#pragma unroll
        for (int kk = 0; kk < 4; kk++) {
            const uint32_t kb = (uint32_t)kk * 32;
            uint32_t A[4];
            ldsm_x4(A, sa + swz(arow128, kb + aq));
            uint32_t Bf[4][4], Bt[2];
#pragma unroll
            for (int nt = 0; nt < 4; nt++)
                ldsm_x4(Bf[nt], sbB + swz(brow128 + (wn + nt * 16) * 128, kb + bq));
            ldsm_x2(Bt, sbB + swz(brow2 + (wn + 64) * 128, kb + bq));
#pragma unroll
            for (int nt = 0; nt < 4; nt++) {
                mma16816(acc[2 * nt],     A, Bf[nt][0], Bf[nt][1]);
                mma16816(acc[2 * nt + 1], A, Bf[nt][2], Bf[nt][3]);
            }
            mma16816(acc[8], A, Bt[0], Bt[1]);
        }
    }

    __syncthreads();
    float* su = (float*)smem;                      // [64][144]
    float* Pa = (float*)(smem + 64 * NUP * 4);     // [64][8]
    float* Pb = Pa + 64 * 8;
    {
        const int r0 = wm + (lid >> 2);
        const int r1 = r0 + 8;
#pragma unroll
        for (int nt = 0; nt < 9; nt++) {
            const int n = wn + nt * 8 + (lid & 3) * 2;
            float b0 = 0.f, b1 = 0.f;
            if (n < NU)     b0 = u_bias(n,     ba, bb, bva, bvb);
            if (n + 1 < NU) b1 = u_bias(n + 1, ba, bb, bva, bvb);
            su[r0 * NUP + n]     = acc[nt][0] + b0;
            su[r0 * NUP + n + 1] = acc[nt][1] + b1;
            su[r1 * NUP + n]     = acc[nt][2] + b0;
            su[r1 * NUP + n + 1] = acc[nt][3] + b1;
        }
    }
    __syncthreads();

    if (tid < 64) {
        const float* u   = su + tid * NUP;
        const float* al  = u;
        const float* be  = u + 4;
        const float* u0a = u + 8;
        const float* u1a = u + 40;
        const float* u0b = u + 72;
        const float* u1b = u + 104;

        float S1a = 0.f, S1b = 0.f;
#pragma unroll
        for (int j = 0; j < 32; j++) {
            const float xa = u1a[j], xa2 = xa * xa;
            const float xb = u1b[j], xb2 = xb * xb;
            S1a += xa2 * xa2 * fabsf(xa);
            S1b += xb2 * xb2 * fabsf(xb);
        }
        float ca[4], cb[4];
#pragma unroll
        for (int k = 0; k < 4; k++) {
            float S0a = 0.f, S0b = 0.f;
#pragma unroll
            for (int i = 0; i < 8; i++) {
                const float xa = u0a[8 * k + i], xa2 = xa * xa;
                const float xb = u0b[8 * k + i], xb2 = xb * xb;
                S0a += xa2 * xa2 * fabsf(xa);
                S0b += xb2 * xb2 * fabsf(xb);
            }
            const float na = fmaxf(exp2f(0.2f * log2f(S0a * S1a)), 1e-12f);
            const float nb = fmaxf(exp2f(0.2f * log2f(S0b * S1b)), 1e-12f);
            ca[k] = al[k] / na;
            cb[k] = be[k] / nb;
        }
#pragma unroll
        for (int ii = 0; ii < 8; ii++) {
            float pa = 0.f, pb = 0.f;
#pragma unroll
            for (int k = 0; k < 4; k++) {
                pa += ca[k] * u0a[8 * k + ii];
                pb += cb[k] * u0b[8 * k + ii];
            }
            Pa[tid * 8 + ii] = pa;
            Pb[tid * 8 + ii] = pb;
        }
    }
    __syncthreads();

#pragma unroll
    for (int e = 0; e < 64; e++) {
        const int idx = tid + e * 256;
        const int m = idx >> 8;
        const int c = idx & 255;
        const int ii = c >> 5;
        const int j  = c & 31;
        const float* u = su + m * NUP;
        mem_new[(size_t)(M0 + m) * MEMSZ + c] =
            mem[(size_t)(M0 + m) * MEMSZ + c] +
            0.25f * (u[40 + j] * Pa[m * 8 + ii] - u[104 + j] * Pb[m * 8 + ii]);
    }
}

// ============================================================================
// Launch
// ============================================================================
extern "C" void kernel_launch(void* const* d_in, const int* in_sizes, int n_in,
                              void* d_out, int out_size)
{
    const float* x   = (const float*)d_in[0];
    const float* h0  = (const float*)d_in[1];
    const float* mem = (const float*)d_in[2];
    const float* Wh  = (const float*)d_in[3];
    const float* bh  = (const float*)d_in[4];
    const float* Wa  = (const float*)d_in[5];
    const float* ba  = (const float*)d_in[6];
    const float* Wb  = (const float*)d_in[7];
    const float* bb  = (const float*)d_in[8];
    const float* Wva = (const float*)d_in[9];
    const float* bva = (const float*)d_in[10];
    const float* Wvb = (const float*)d_in[11];
    const float* bvb = (const float*)d_in[12];

    float* out     = (float*)d_out;
    float* mem_new = out;                              // [B, 256]
    float* h       = out + (size_t)B_ROWS * MEMSZ;     // [B, 1024]

    cudaFuncSetAttribute(gemm1_mma, cudaFuncAttributeMaxDynamicSharedMemorySize, G1_SMEM);
    cudaFuncSetAttribute(gemm2_mma, cudaFuncAttributeMaxDynamicSharedMemorySize, G2_SMEM);

    convA_kernel<<<(B_ROWS * (KTOT / 4)) / 256, 256>>>(x, h0, mem);
    convW_kernel<<<(HID * (KTOT / 4)) / 256, 256>>>(Wh);
    convW2_kernel<<<(NUP * (HM / 4) + 255) / 256, 256>>>(Wa, Wb, Wva, Wvb);
    gemm1_mma<<<dim3(HID / G1_TN, B_ROWS / G1_TM), 128, G1_SMEM>>>(bh, h);
    gemm2_mma<<<B_ROWS / G2_TM, 256, G2_SMEM>>>(mem, ba, bb, bva, bvb, mem_new);
}

// round 8
// speedup vs baseline: 1.6324x; 1.0245x over previous
#include <cuda_runtime.h>
#include <cuda_bf16.h>
#include <cuda_fp16.h>
#include <cstdint>

#define B_ROWS 8192
#define INP    1024
#define HID    1024
#define MEMSZ  256
#define KTOT   2304   // INP + HID + MEMSZ
#define HM     1280   // HID + MEMSZ
#define A2K    2560   // hi|lo concat for gemm2 A
#define NU     136
#define NUP    144

// ------------------- device scratch (static: no allocation) -------------------
__device__ __align__(16) __half        g_A16[(size_t)B_ROWS * (2 * KTOT)]; // A hi|lo fp16
__device__ __align__(16) __half        g_W16[(size_t)HID * KTOT];          // W fp16 (rounded)
__device__ __align__(16) __nv_bfloat16 g_A2bf[(size_t)B_ROWS * A2K];       // gemm2 A hi|lo bf16
__device__ __align__(16) __nv_bfloat16 g_W2bf[(size_t)NUP * A2K];          // gemm2 W hi|lo bf16

// ============================ helpers ============================
__device__ __forceinline__ uint32_t smem_u32(const void* p) {
    uint32_t a;
    asm("{ .reg .u64 t; cvta.to.shared.u64 t, %1; cvt.u32.u64 %0, t; }" : "=r"(a) : "l"(p));
    return a;
}
__device__ __forceinline__ uint32_t swz(uint32_t rowbase128, uint32_t q) {
    return rowbase128 + (q ^ ((rowbase128 >> 3) & 0x70u));
}

#define CP_ASYNC16(saddr, gptr) \
    asm volatile("cp.async.cg.shared.global [%0], [%1], 16;" :: "r"(saddr), "l"(gptr))
#define CP_COMMIT() asm volatile("cp.async.commit_group;" ::: "memory")
#define CP_WAIT1()  asm volatile("cp.async.wait_group 1;" ::: "memory")

__device__ __forceinline__ void ldsm_x4(uint32_t* r, uint32_t addr) {
    asm volatile("ldmatrix.sync.aligned.m8n8.x4.shared.b16 {%0,%1,%2,%3}, [%4];"
                 : "=r"(r[0]), "=r"(r[1]), "=r"(r[2]), "=r"(r[3]) : "r"(addr));
}
__device__ __forceinline__ void ldsm_x2(uint32_t* r, uint32_t addr) {
    asm volatile("ldmatrix.sync.aligned.m8n8.x2.shared.b16 {%0,%1}, [%2];"
                 : "=r"(r[0]), "=r"(r[1]) : "r"(addr));
}
__device__ __forceinline__ void mma16816(float* d, const uint32_t* a,
                                         uint32_t b0, uint32_t b1) {
    asm volatile("mma.sync.aligned.m16n8k16.row.col.f32.bf16.bf16.f32 "
                 "{%0,%1,%2,%3}, {%4,%5,%6,%7}, {%8,%9}, {%0,%1,%2,%3};"
                 : "+f"(d[0]), "+f"(d[1]), "+f"(d[2]), "+f"(d[3])
                 : "r"(a[0]), "r"(a[1]), "r"(a[2]), "r"(a[3]), "r"(b0), "r"(b1));
}
__device__ __forceinline__ void mma_f16(float* d, const uint32_t* a,
                                        uint32_t b0, uint32_t b1) {
    asm volatile("mma.sync.aligned.m16n8k16.row.col.f32.f16.f16.f32 "
                 "{%0,%1,%2,%3}, {%4,%5,%6,%7}, {%8,%9}, {%0,%1,%2,%3};"
                 : "+f"(d[0]), "+f"(d[1]), "+f"(d[2]), "+f"(d[3])
                 : "r"(a[0]), "r"(a[1]), "r"(a[2]), "r"(a[3]), "r"(b0), "r"(b1));
}

// ============================================================================
// Fused conversion kernel (one launch): block ranges -> A, W, W2.
// ============================================================================
struct bf4 { __nv_bfloat162 a, b; };
struct hf4 { __half2 a, b; };

#define NBLK_A  (B_ROWS * (KTOT / 4) / 256)           // 18432
#define NBLK_W  (HID * (KTOT / 4) / 256)              // 2304
#define NBLK_W2 ((NUP * (HM / 4) + 255) / 256)        // 180

__device__ __forceinline__ const float* u_wrow(int n, const float* Wa, const float* Wb,
                                               const float* Wva, const float* Wvb)
{
    if (n < 4)  return Wa  + (size_t)n * HM;
    if (n < 8)  return Wb  + (size_t)(n - 4) * HM;
    if (n < 72) return Wva + (size_t)(n - 8) * HM;
    return Wvb + (size_t)(n - 72) * HM;
}
__device__ __forceinline__ float u_bias(int n, const float* ba, const float* bb,
                                        const float* bva, const float* bvb)
{
    if (n < 4)  return ba[n];
    if (n < 8)  return bb[n - 4];
    if (n < 72) return bva[n - 8];
    return bvb[n - 72];
}

__global__ void conv_all(const float* __restrict__ x, const float* __restrict__ h0,
                         const float* __restrict__ mem, const float* __restrict__ Wh,
                         const float* __restrict__ Wa, const float* __restrict__ Wb,
                         const float* __restrict__ Wva, const float* __restrict__ Wvb)
{
    const int blk = blockIdx.x;
    if (blk < NBLK_A) {
        // ---- A: fp32 -> fp16 hi + exact fp16 residual lo ----
        const int gid = blk * 256 + threadIdx.x;
        const int row = gid / (KTOT / 4);
        const int k   = (gid % (KTOT / 4)) * 4;
        float4 v;
        if (k < INP)            v = *(const float4*)(x   + (size_t)row * INP + k);
        else if (k < INP + HID) v = *(const float4*)(h0  + (size_t)row * HID + (k - INP));
        else                    v = *(const float4*)(mem + (size_t)row * MEMSZ + (k - INP - HID));

        const __half a0 = __float2half_rn(v.x);
        const __half a1 = __float2half_rn(v.y);
        const __half a2 = __float2half_rn(v.z);
        const __half a3 = __float2half_rn(v.w);
        hf4 hi, lo;
        hi.a = __half2(a0, a1); hi.b = __half2(a2, a3);
        lo.a = __half2(__float2half_rn(v.x - __half2float(a0)),
                       __float2half_rn(v.y - __half2float(a1)));
        lo.b = __half2(__float2half_rn(v.z - __half2float(a2)),
                       __float2half_rn(v.w - __half2float(a3)));
        __half* dst = g_A16 + (size_t)row * (2 * KTOT) + k;
        *(hf4*)dst          = hi;
        *(hf4*)(dst + KTOT) = lo;

        if (k >= INP + HID) {   // memory slice feeds gemm2's A (cols 1024..1280)
            const int km = k - (INP + HID);
            const __nv_bfloat16 h0b = __float2bfloat16_rn(v.x);
            const __nv_bfloat16 h1b = __float2bfloat16_rn(v.y);
            const __nv_bfloat16 h2b = __float2bfloat16_rn(v.z);
            const __nv_bfloat16 h3b = __float2bfloat16_rn(v.w);
            bf4 bhi, blo;
            bhi.a = __nv_bfloat162(h0b, h1b);
            bhi.b = __nv_bfloat162(h2b, h3b);
            blo.a = __nv_bfloat162(__float2bfloat16_rn(v.x - __bfloat162float(h0b)),
                                   __float2bfloat16_rn(v.y - __bfloat162float(h1b)));
            blo.b = __nv_bfloat162(__float2bfloat16_rn(v.z - __bfloat162float(h2b)),
                                   __float2bfloat16_rn(v.w - __bfloat162float(h3b)));
            __nv_bfloat16* d = g_A2bf + (size_t)row * A2K + HID + km;
            *(bf4*)d        = bhi;
            *(bf4*)(d + HM) = blo;
        }
    } else if (blk < NBLK_A + NBLK_W) {
        // ---- W: fp32 -> fp16 single rounding ----
        const int gid = (blk - NBLK_A) * 256 + threadIdx.x;
        const int row = gid / (KTOT / 4);
        const int k   = (gid % (KTOT / 4)) * 4;
        const float4 v = *(const float4*)(Wh + (size_t)row * KTOT + k);
        hf4 w;
        w.a = __half2(__float2half_rn(v.x), __float2half_rn(v.y));
        w.b = __half2(__float2half_rn(v.z), __float2half_rn(v.w));
        *(hf4*)(g_W16 + (size_t)row * KTOT + k) = w;
    } else {
        // ---- W2: packed [144][1280] -> bf16 hi|lo ----
        const int gid = (blk - NBLK_A - NBLK_W) * 256 + threadIdx.x;
        if (gid >= NUP * (HM / 4)) return;
        const int n = gid / (HM / 4);
        const int k = (gid % (HM / 4)) * 4;
        float4 v = make_float4(0.f, 0.f, 0.f, 0.f);
        if (n < NU) v = *(const float4*)(u_wrow(n, Wa, Wb, Wva, Wvb) + k);
        const __nv_bfloat16 h0b = __float2bfloat16_rn(v.x);
        const __nv_bfloat16 h1b = __float2bfloat16_rn(v.y);
        const __nv_bfloat16 h2b = __float2bfloat16_rn(v.z);
        const __nv_bfloat16 h3b = __float2bfloat16_rn(v.w);
        bf4 hi, lo;
        hi.a = __nv_bfloat162(h0b, h1b);
        hi.b = __nv_bfloat162(h2b, h3b);
        lo.a = __nv_bfloat162(__float2bfloat16_rn(v.x - __bfloat162float(h0b)),
                              __float2bfloat16_rn(v.y - __bfloat162float(h1b)));
        lo.b = __nv_bfloat162(__float2bfloat16_rn(v.z - __bfloat162float(h2b)),
                              __float2bfloat16_rn(v.w - __bfloat162float(h3b)));
        __nv_bfloat16* dst = g_W2bf + (size_t)n * A2K + k;
        *(bf4*)dst        = hi;
        *(bf4*)(dst + HM) = lo;
    }
}

// ============================================================================
// GEMM1: fp16 2-product split on A (Ahi + Alo, B rounded), single fp32 acc.
// h = relu(A @ W^T + b). CTA 64x128, 128 threads (2Mx2N warps), 2 CTAs/SM.
// 3-stage pipeline, ONE __syncthreads per chunk (CUTLASS multistage order).
// Stage: Ahi(8K) | Alo(8K) | B(16K) = 32KB; 3 stages = 96KB.
// ============================================================================
#define G1_TM 64
#define G1_TN 128
#define G1_NC 36
#define G1_AHI 0
#define G1_ALO 8192
#define G1_B   16384
#define G1_STG 32768
#define G1_SMEM (3 * G1_STG)   // 98304

__global__ __launch_bounds__(128, 2)
void gemm1_mma(const float* __restrict__ bh, float* __restrict__ hout)
{
    extern __shared__ __align__(1024) unsigned char smem[];
    const uint32_t sbase = smem_u32(smem);
    const int tid = threadIdx.x;
    const int wid = tid >> 5;
    const int lid = tid & 31;
    const int N0 = blockIdx.x * G1_TN;
    const int M0 = blockIdx.y * G1_TM;

    // ---------- producer addressing ----------
    const char* pA[4];  uint32_t sA[4];   // 64 A rows x 8 slots = 512
    const char* pB[8];  uint32_t sB[8];   // 128 B rows x 8 slots = 1024
#pragma unroll
    for (int r = 0; r < 4; r++) {
        const int idx = tid + 128 * r, row = idx >> 3, sl = idx & 7;
        pA[r] = (const char*)g_A16 + (size_t)(M0 + row) * (KTOT * 4) + sl * 16;
        sA[r] = swz((uint32_t)row * 128, (uint32_t)sl * 16);
    }
#pragma unroll
    for (int r = 0; r < 8; r++) {
        const int idx = tid + 128 * r, row = idx >> 3, sl = idx & 7;
        pB[r] = (const char*)g_W16 + (size_t)(N0 + row) * (KTOT * 2) + sl * 16;
        sB[r] = swz((uint32_t)row * 128, (uint32_t)sl * 16);
    }

    auto issue_load = [&](int kc, int stage) {
        const uint32_t st = sbase + stage * G1_STG;
        const uint32_t cb = (uint32_t)kc * 128;
#pragma unroll
        for (int r = 0; r < 4; r++) {
            CP_ASYNC16(st + G1_AHI + sA[r], pA[r] + cb);
            CP_ASYNC16(st + G1_ALO + sA[r], pA[r] + cb + KTOT * 2);
        }
#pragma unroll
        for (int r = 0; r < 8; r++)
            CP_ASYNC16(st + G1_B + sB[r], pB[r] + cb);
        CP_COMMIT();
    };

    // ---------- consumer addressing ----------
    const int wm = (wid & 1) * 32;
    const int wn = (wid >> 1) * 64;
    const uint32_t arow128 = (uint32_t)(wm + (lid & 15)) * 128;
    const uint32_t aq      = (uint32_t)((lid >> 4) * 16);
    const uint32_t brow128 = (uint32_t)(wn + (lid & 7) + ((lid >> 4) & 1) * 8) * 128;
    const uint32_t bq      = (uint32_t)(((lid >> 3) & 1) * 16);

    float acc[2][8][4];
#pragma unroll
    for (int i = 0; i < 2; i++)
#pragma unroll
        for (int j = 0; j < 8; j++)
#pragma unroll
            for (int q = 0; q < 4; q++) acc[i][j][q] = 0.f;

    issue_load(0, 0);
    issue_load(1, 1);

#pragma unroll 1
    for (int kc = 0; kc < G1_NC; kc++) {
        CP_WAIT1();
        __syncthreads();   // all warps done with chunk kc-1 -> slot (kc+2)%3 is free
        if (kc + 2 < G1_NC) issue_load(kc + 2, (kc + 2) % 3);
        else CP_COMMIT();  // keep group counting consistent

        const uint32_t st = sbase + (kc % 3) * G1_STG;
#pragma unroll
        for (int kk = 0; kk < 4; kk++) {
            const uint32_t kb = (uint32_t)kk * 32;
            uint32_t Ah[2][4], Al[2][4], B[4][4];
#pragma unroll
            for (int mt = 0; mt < 2; mt++) {
                ldsm_x4(Ah[mt], st + G1_AHI + swz(arow128 + mt * 16 * 128, kb + aq));
                ldsm_x4(Al[mt], st + G1_ALO + swz(arow128 + mt * 16 * 128, kb + aq));
            }
#pragma unroll
            for (int nt = 0; nt < 4; nt++)
                ldsm_x4(B[nt], st + G1_B + swz(brow128 + nt * 16 * 128, kb + bq));
#pragma unroll
            for (int mt = 0; mt < 2; mt++)
#pragma unroll
                for (int nt = 0; nt < 4; nt++) {
                    mma_f16(acc[mt][2 * nt],     Ah[mt], B[nt][0], B[nt][1]);
                    mma_f16(acc[mt][2 * nt + 1], Ah[mt], B[nt][2], B[nt][3]);
                    mma_f16(acc[mt][2 * nt],     Al[mt], B[nt][0], B[nt][1]);
                    mma_f16(acc[mt][2 * nt + 1], Al[mt], B[nt][2], B[nt][3]);
                }
        }
    }

    // ---------- epilogue: bias + relu; fp32 h + bf16 hi/lo into g_A2bf ----------
#pragma unroll
    for (int mt = 0; mt < 2; mt++) {
        const int m = M0 + wm + mt * 16 + (lid >> 2);
#pragma unroll
        for (int nt = 0; nt < 8; nt++) {
            const int n = N0 + wn + nt * 8 + (lid & 3) * 2;
            const float2 bv = *(const float2*)(bh + n);
            float2 v0, v1;
            v0.x = acc[mt][nt][0] + bv.x; v0.y = acc[mt][nt][1] + bv.y;
            v1.x = acc[mt][nt][2] + bv.x; v1.y = acc[mt][nt][3] + bv.y;
            v0.x = v0.x > 0.f ? v0.x : 0.f; v0.y = v0.y > 0.f ? v0.y : 0.f;
            v1.x = v1.x > 0.f ? v1.x : 0.f; v1.y = v1.y > 0.f ? v1.y : 0.f;
            *(float2*)(hout + (size_t)m * HID + n)       = v0;
            *(float2*)(hout + (size_t)(m + 8) * HID + n) = v1;

            const __nv_bfloat16 h00 = __float2bfloat16_rn(v0.x);
            const __nv_bfloat16 h01 = __float2bfloat16_rn(v0.y);
            const __nv_bfloat16 h10 = __float2bfloat16_rn(v1.x);
            const __nv_bfloat16 h11 = __float2bfloat16_rn(v1.y);
            __nv_bfloat16* d0 = g_A2bf + (size_t)m * A2K + n;
            __nv_bfloat16* d1 = g_A2bf + (size_t)(m + 8) * A2K + n;
            *(__nv_bfloat162*)d0 = __nv_bfloat162(h00, h01);
            *(__nv_bfloat162*)d1 = __nv_bfloat162(h10, h11);
            *(__nv_bfloat162*)(d0 + HM) =
                __nv_bfloat162(__float2bfloat16_rn(v0.x - __bfloat162float(h00)),
                               __float2bfloat16_rn(v0.y - __bfloat162float(h01)));
            *(__nv_bfloat162*)(d1 + HM) =
                __nv_bfloat162(__float2bfloat16_rn(v1.x - __bfloat162float(h10)),
                               __float2bfloat16_rn(v1.y - __bfloat162float(h11)));
        }
    }
}

// ============================================================================
// GEMM2 via mma.sync + fused finish (proven round-5 version, unchanged).
// ============================================================================
#define NSTAGE 3
#define G2_TM 64
#define G2_NCHUNK 60
#define G2_SA (G2_TM * 128)
#define G2_SB (NUP * 128)
#define G2_STG (G2_SA + G2_SB)
#define G2_SMEM (3 * G2_STG)

__global__ __launch_bounds__(256, 1)
void gemm2_mma(const float* __restrict__ mem,
               const float* __restrict__ ba, const float* __restrict__ bb,
               const float* __restrict__ bva, const float* __restrict__ bvb,
               float* __restrict__ mem_new)
{
    extern __shared__ __align__(1024) unsigned char smem[];
    const uint32_t sbase = smem_u32(smem);
    const int tid = threadIdx.x;
    const int wid = tid >> 5;
    const int lid = tid & 31;
    const int M0 = blockIdx.x * G2_TM;

    const int prow = tid >> 3;
    const int pc   = tid & 7;
    const char* Ag = (const char*)g_A2bf + (size_t)(M0 + prow) * (A2K * 2) + pc * 16;
    const uint32_t sAoff = swz((uint32_t)prow * 128, (uint32_t)pc * 16);

    auto issue_load = [&](int kc, int stage) {
        uint32_t aoff, boff;
        if (kc < 20)      { aoff = kc * 128;               boff = kc * 128; }
        else if (kc < 40) { aoff = 2560 + (kc - 20) * 128; boff = (kc - 20) * 128; }
        else              { aoff = (kc - 40) * 128;        boff = 2560 + (kc - 40) * 128; }
        const uint32_t sa  = sbase + stage * G2_STG;
        const uint32_t sbB = sa + G2_SA;
#pragma unroll
        for (int r = 0; r < 2; r++)
            CP_ASYNC16(sa + sAoff + r * 4096, Ag + aoff + (size_t)r * (32 * A2K * 2));
#pragma unroll
        for (int r = 0; r < 5; r++) {
            const int idx = tid + 256 * r;
            if (idx < NUP * 8) {
                const int row = idx >> 3, c = idx & 7;
                CP_ASYNC16(sbB + swz((uint32_t)row * 128, (uint32_t)c * 16),
                           (const char*)g_W2bf + (size_t)row * (A2K * 2) + c * 16 + boff);
            }
        }
        CP_COMMIT();
    };

    const int wm = (wid & 3) * 16;
    const int wn = (wid >> 2) * 72;
    const uint32_t arow128 = (uint32_t)(wm + (lid & 15)) * 128;
    const uint32_t aq      = (uint32_t)((lid >> 4) * 16);
    const uint32_t brow128 = (uint32_t)((lid & 7) + ((lid >> 4) & 1) * 8) * 128;
    const uint32_t bq      = (uint32_t)(((lid >> 3) & 1) * 16);
    const uint32_t brow2   = (uint32_t)(lid & 7) * 128;

    float acc[9][4];
#pragma unroll
    for (int j = 0; j < 9; j++)
#pragma unroll
        for (int q = 0; q < 4; q++) acc[j][q] = 0.f;

    issue_load(0, 0);
    issue_load(1, 1);

#pragma unroll 1
    for (int kc = 0; kc < G2_NCHUNK; kc++) {
        CP_WAIT1();
        __syncthreads();
        if (kc + 2 < G2_NCHUNK) issue_load(kc + 2, (kc + 2) % NSTAGE);
        else CP_COMMIT();

        const uint32_t sa  = sbase + (kc % NSTAGE) * G2_STG;
        const uint32_t sbB = sa + G2_SA;
#pragma unroll
        for (int kk = 0; kk < 4; kk++) {
            const uint32_t kb = (uint32_t)kk * 32;
            uint32_t A[4];
            ldsm_x4(A, sa + swz(arow128, kb + aq));
            uint32_t Bf[4][4], Bt[2];
#pragma unroll
            for (int nt = 0; nt < 4; nt++)
                ldsm_x4(Bf[nt], sbB + swz(brow128 + (wn + nt * 16) * 128, kb + bq));
            ldsm_x2(Bt, sbB + swz(brow2 + (wn + 64) * 128, kb + bq));
#pragma unroll
            for (int nt = 0; nt < 4; nt++) {
                mma16816(acc[2 * nt],     A, Bf[nt][0], Bf[nt][1]);
                mma16816(acc[2 * nt + 1], A, Bf[nt][2], Bf[nt][3]);
            }
            mma16816(acc[8], A, Bt[0], Bt[1]);
        }
    }

    __syncthreads();
    float* su = (float*)smem;                      // [64][144]
    float* Pa = (float*)(smem + 64 * NUP * 4);     // [64][8]
    float* Pb = Pa + 64 * 8;
    {
        const int r0 = wm + (lid >> 2);
        const int r1 = r0 + 8;
#pragma unroll
        for (int nt = 0; nt < 9; nt++) {
            const int n = wn + nt * 8 + (lid & 3) * 2;
            float b0 = 0.f, b1 = 0.f;
            if (n < NU)     b0 = u_bias(n,     ba, bb, bva, bvb);
            if (n + 1 < NU) b1 = u_bias(n + 1, ba, bb, bva, bvb);
            su[r0 * NUP + n]     = acc[nt][0] + b0;
            su[r0 * NUP + n + 1] = acc[nt][1] + b1;
            su[r1 * NUP + n]     = acc[nt][2] + b0;
            su[r1 * NUP + n + 1] = acc[nt][3] + b1;
        }
    }
    __syncthreads();

    if (tid < 64) {
        const float* u   = su + tid * NUP;
        const float* al  = u;
        const float* be  = u + 4;
        const float* u0a = u + 8;
        const float* u1a = u + 40;
        const float* u0b = u + 72;
        const float* u1b = u + 104;

        float S1a = 0.f, S1b = 0.f;
#pragma unroll
        for (int j = 0; j < 32; j++) {
            const float xa = u1a[j], xa2 = xa * xa;
            const float xb = u1b[j], xb2 = xb * xb;
            S1a += xa2 * xa2 * fabsf(xa);
            S1b += xb2 * xb2 * fabsf(xb);
        }
        float ca[4], cb[4];
#pragma unroll
        for (int k = 0; k < 4; k++) {
            float S0a = 0.f, S0b = 0.f;
#pragma unroll
            for (int i = 0; i < 8; i++) {
                const float xa = u0a[8 * k + i], xa2 = xa * xa;
                const float xb = u0b[8 * k + i], xb2 = xb * xb;
                S0a += xa2 * xa2 * fabsf(xa);
                S0b += xb2 * xb2 * fabsf(xb);
            }
            const float na = fmaxf(exp2f(0.2f * log2f(S0a * S1a)), 1e-12f);
            const float nb = fmaxf(exp2f(0.2f * log2f(S0b * S1b)), 1e-12f);
            ca[k] = al[k] / na;
            cb[k] = be[k] / nb;
        }
#pragma unroll
        for (int ii = 0; ii < 8; ii++) {
            float pa = 0.f, pb = 0.f;
#pragma unroll
            for (int k = 0; k < 4; k++) {
                pa += ca[k] * u0a[8 * k + ii];
                pb += cb[k] * u0b[8 * k + ii];
            }
            Pa[tid * 8 + ii] = pa;
            Pb[tid * 8 + ii] = pb;
        }
    }
    __syncthreads();

#pragma unroll
    for (int e = 0; e < 64; e++) {
        const int idx = tid + e * 256;
        const int m = idx >> 8;
        const int c = idx & 255;
        const int ii = c >> 5;
        const int j  = c & 31;
        const float* u = su + m * NUP;
        mem_new[(size_t)(M0 + m) * MEMSZ + c] =
            mem[(size_t)(M0 + m) * MEMSZ + c] +
            0.25f * (u[40 + j] * Pa[m * 8 + ii] - u[104 + j] * Pb[m * 8 + ii]);
    }
}

// ============================================================================
// Launch
// ============================================================================
extern "C" void kernel_launch(void* const* d_in, const int* in_sizes, int n_in,
                              void* d_out, int out_size)
{
    const float* x   = (const float*)d_in[0];
    const float* h0  = (const float*)d_in[1];
    const float* mem = (const float*)d_in[2];
    const float* Wh  = (const float*)d_in[3];
    const float* bh  = (const float*)d_in[4];
    const float* Wa  = (const float*)d_in[5];
    const float* ba  = (const float*)d_in[6];
    const float* Wb  = (const float*)d_in[7];
    const float* bb  = (const float*)d_in[8];
    const float* Wva = (const float*)d_in[9];
    const float* bva = (const float*)d_in[10];
    const float* Wvb = (const float*)d_in[11];
    const float* bvb = (const float*)d_in[12];

    float* out     = (float*)d_out;
    float* mem_new = out;                              // [B, 256]
    float* h       = out + (size_t)B_ROWS * MEMSZ;     // [B, 1024]

    cudaFuncSetAttribute(gemm1_mma, cudaFuncAttributeMaxDynamicSharedMemorySize, G1_SMEM);
    cudaFuncSetAttribute(gemm2_mma, cudaFuncAttributeMaxDynamicSharedMemorySize, G2_SMEM);

    conv_all<<<NBLK_A + NBLK_W + NBLK_W2, 256>>>(x, h0, mem, Wh, Wa, Wb, Wva, Wvb);
    gemm1_mma<<<dim3(HID / G1_TN, B_ROWS / G1_TM), 128, G1_SMEM>>>(bh, h);
    gemm2_mma<<<B_ROWS / G2_TM, 256, G2_SMEM>>>(mem, ba, bb, bva, bvb, mem_new);
}

// round 9
// speedup vs baseline: 2.2869x; 1.4009x over previous
#include <cuda_runtime.h>
#include <cuda_bf16.h>
#include <cuda_fp16.h>
#include <cstdint>

#define B_ROWS 8192
#define INP    1024
#define HID    1024
#define MEMSZ  256
#define KTOT   2304   // INP + HID + MEMSZ
#define HM     1280   // HID + MEMSZ
#define A2K    2560   // hi|lo concat for gemm2 A
#define NU     136
#define NUP    144

// ------------------- device scratch (static: no allocation) -------------------
__device__ __align__(16) __half        g_A16[(size_t)B_ROWS * KTOT];   // A fp16 (rounded)
__device__ __align__(16) __half        g_W16[(size_t)HID * KTOT];      // W fp16 (rounded)
__device__ __align__(16) __nv_bfloat16 g_A2bf[(size_t)B_ROWS * A2K];   // gemm2 A hi|lo bf16
__device__ __align__(16) __nv_bfloat16 g_W2bf[(size_t)NUP * A2K];      // gemm2 W hi|lo bf16

// ============================ helpers ============================
__device__ __forceinline__ uint32_t smem_u32(const void* p) {
    uint32_t a;
    asm("{ .reg .u64 t; cvta.to.shared.u64 t, %1; cvt.u32.u64 %0, t; }" : "=r"(a) : "l"(p));
    return a;
}
__device__ __forceinline__ uint32_t swz(uint32_t rowbase128, uint32_t q) {
    return rowbase128 + (q ^ ((rowbase128 >> 3) & 0x70u));
}

#define CP_ASYNC16(saddr, gptr) \
    asm volatile("cp.async.cg.shared.global [%0], [%1], 16;" :: "r"(saddr), "l"(gptr))
#define CP_COMMIT() asm volatile("cp.async.commit_group;" ::: "memory")
#define CP_WAIT1()  asm volatile("cp.async.wait_group 1;" ::: "memory")

__device__ __forceinline__ void ldsm_x4(uint32_t* r, uint32_t addr) {
    asm volatile("ldmatrix.sync.aligned.m8n8.x4.shared.b16 {%0,%1,%2,%3}, [%4];"
                 : "=r"(r[0]), "=r"(r[1]), "=r"(r[2]), "=r"(r[3]) : "r"(addr));
}
__device__ __forceinline__ void ldsm_x2(uint32_t* r, uint32_t addr) {
    asm volatile("ldmatrix.sync.aligned.m8n8.x2.shared.b16 {%0,%1}, [%2];"
                 : "=r"(r[0]), "=r"(r[1]) : "r"(addr));
}
__device__ __forceinline__ void mma16816(float* d, const uint32_t* a,
                                         uint32_t b0, uint32_t b1) {
    asm volatile("mma.sync.aligned.m16n8k16.row.col.f32.bf16.bf16.f32 "
                 "{%0,%1,%2,%3}, {%4,%5,%6,%7}, {%8,%9}, {%0,%1,%2,%3};"
                 : "+f"(d[0]), "+f"(d[1]), "+f"(d[2]), "+f"(d[3])
                 : "r"(a[0]), "r"(a[1]), "r"(a[2]), "r"(a[3]), "r"(b0), "r"(b1));
}
__device__ __forceinline__ void mma_f16(float* d, const uint32_t* a,
                                        uint32_t b0, uint32_t b1) {
    asm volatile("mma.sync.aligned.m16n8k16.row.col.f32.f16.f16.f32 "
                 "{%0,%1,%2,%3}, {%4,%5,%6,%7}, {%8,%9}, {%0,%1,%2,%3};"
                 : "+f"(d[0]), "+f"(d[1]), "+f"(d[2]), "+f"(d[3])
                 : "r"(a[0]), "r"(a[1]), "r"(a[2]), "r"(a[3]), "r"(b0), "r"(b1));
}

// ============================================================================
// Fused conversion kernel (one launch): block ranges -> A, W, W2.
// ============================================================================
struct bf4 { __nv_bfloat162 a, b; };
struct hf4 { __half2 a, b; };

#define NBLK_A  (B_ROWS * (KTOT / 4) / 256)           // 18432
#define NBLK_W  (HID * (KTOT / 4) / 256)              // 2304
#define NBLK_W2 ((NUP * (HM / 4) + 255) / 256)        // 180

__device__ __forceinline__ const float* u_wrow(int n, const float* Wa, const float* Wb,
                                               const float* Wva, const float* Wvb)
{
    if (n < 4)  return Wa  + (size_t)n * HM;
    if (n < 8)  return Wb  + (size_t)(n - 4) * HM;
    if (n < 72) return Wva + (size_t)(n - 8) * HM;
    return Wvb + (size_t)(n - 72) * HM;
}
__device__ __forceinline__ float u_bias(int n, const float* ba, const float* bb,
                                        const float* bva, const float* bvb)
{
    if (n < 4)  return ba[n];
    if (n < 8)  return bb[n - 4];
    if (n < 72) return bva[n - 8];
    return bvb[n - 72];
}

__global__ void conv_all(const float* __restrict__ x, const float* __restrict__ h0,
                         const float* __restrict__ mem, const float* __restrict__ Wh,
                         const float* __restrict__ Wa, const float* __restrict__ Wb,
                         const float* __restrict__ Wva, const float* __restrict__ Wvb)
{
    const int blk = blockIdx.x;
    if (blk < NBLK_A) {
        // ---- A: fp32 -> fp16 (single rounding) ----
        const int gid = blk * 256 + threadIdx.x;
        const int row = gid / (KTOT / 4);
        const int k   = (gid % (KTOT / 4)) * 4;
        float4 v;
        if (k < INP)            v = *(const float4*)(x   + (size_t)row * INP + k);
        else if (k < INP + HID) v = *(const float4*)(h0  + (size_t)row * HID + (k - INP));
        else                    v = *(const float4*)(mem + (size_t)row * MEMSZ + (k - INP - HID));

        hf4 a16;
        a16.a = __half2(__float2half_rn(v.x), __float2half_rn(v.y));
        a16.b = __half2(__float2half_rn(v.z), __float2half_rn(v.w));
        *(hf4*)(g_A16 + (size_t)row * KTOT + k) = a16;

        if (k >= INP + HID) {   // memory slice feeds gemm2's A (cols 1024..1280)
            const int km = k - (INP + HID);
            const __nv_bfloat16 h0b = __float2bfloat16_rn(v.x);
            const __nv_bfloat16 h1b = __float2bfloat16_rn(v.y);
            const __nv_bfloat16 h2b = __float2bfloat16_rn(v.z);
            const __nv_bfloat16 h3b = __float2bfloat16_rn(v.w);
            bf4 bhi, blo;
            bhi.a = __nv_bfloat162(h0b, h1b);
            bhi.b = __nv_bfloat162(h2b, h3b);
            blo.a = __nv_bfloat162(__float2bfloat16_rn(v.x - __bfloat162float(h0b)),
                                   __float2bfloat16_rn(v.y - __bfloat162float(h1b)));
            blo.b = __nv_bfloat162(__float2bfloat16_rn(v.z - __bfloat162float(h2b)),
                                   __float2bfloat16_rn(v.w - __bfloat162float(h3b)));
            __nv_bfloat16* d = g_A2bf + (size_t)row * A2K + HID + km;
            *(bf4*)d        = bhi;
            *(bf4*)(d + HM) = blo;
        }
    } else if (blk < NBLK_A + NBLK_W) {
        // ---- W: fp32 -> fp16 single rounding ----
        const int gid = (blk - NBLK_A) * 256 + threadIdx.x;
        const int row = gid / (KTOT / 4);
        const int k   = (gid % (KTOT / 4)) * 4;
        const float4 v = *(const float4*)(Wh + (size_t)row * KTOT + k);
        hf4 w;
        w.a = __half2(__float2half_rn(v.x), __float2half_rn(v.y));
        w.b = __half2(__float2half_rn(v.z), __float2half_rn(v.w));
        *(hf4*)(g_W16 + (size_t)row * KTOT + k) = w;
    } else {
        // ---- W2: packed [144][1280] -> bf16 hi|lo ----
        const int gid = (blk - NBLK_A - NBLK_W) * 256 + threadIdx.x;
        if (gid >= NUP * (HM / 4)) return;
        const int n = gid / (HM / 4);
        const int k = (gid % (HM / 4)) * 4;
        float4 v = make_float4(0.f, 0.f, 0.f, 0.f);
        if (n < NU) v = *(const float4*)(u_wrow(n, Wa, Wb, Wva, Wvb) + k);
        const __nv_bfloat16 h0b = __float2bfloat16_rn(v.x);
        const __nv_bfloat16 h1b = __float2bfloat16_rn(v.y);
        const __nv_bfloat16 h2b = __float2bfloat16_rn(v.z);
        const __nv_bfloat16 h3b = __float2bfloat16_rn(v.w);
        bf4 hi, lo;
        hi.a = __nv_bfloat162(h0b, h1b);
        hi.b = __nv_bfloat162(h2b, h3b);
        lo.a = __nv_bfloat162(__float2bfloat16_rn(v.x - __bfloat162float(h0b)),
                              __float2bfloat16_rn(v.y - __bfloat162float(h1b)));
        lo.b = __nv_bfloat162(__float2bfloat16_rn(v.z - __bfloat162float(h2b)),
                              __float2bfloat16_rn(v.w - __bfloat162float(h3b)));
        __nv_bfloat16* dst = g_W2bf + (size_t)n * A2K + k;
        *(bf4*)dst        = hi;
        *(bf4*)(dst + HM) = lo;
    }
}

// ============================================================================
// GEMM1: pure fp16, single product. h = relu(A @ W^T + b).
// CTA 128x128, 128 threads (4 warps, each 64x64), 2 CTAs/SM.
// 3-stage pipeline, ONE __syncthreads per chunk. Stage: A(16K)|B(16K)=32KB.
// ============================================================================
#define G1_TM 128
#define G1_TN 128
#define G1_NC 36
#define G1_A   0
#define G1_B   16384
#define G1_STG 32768
#define G1_SMEM (3 * G1_STG)   // 98304

__global__ __launch_bounds__(128, 2)
void gemm1_mma(const float* __restrict__ bh, float* __restrict__ hout)
{
    extern __shared__ __align__(1024) unsigned char smem[];
    const uint32_t sbase = smem_u32(smem);
    const int tid = threadIdx.x;
    const int wid = tid >> 5;
    const int lid = tid & 31;
    const int N0 = blockIdx.x * G1_TN;   // fast index: 8 N-tiles share A rows
    const int M0 = blockIdx.y * G1_TM;

    // ---------- producer addressing: A 128 rows, B 128 rows, 8 slots each ----
    const char* pA[8];  uint32_t sAo[8];
    const char* pB[8];  uint32_t sBo[8];
#pragma unroll
    for (int r = 0; r < 8; r++) {
        const int idx = tid + 128 * r, row = idx >> 3, sl = idx & 7;
        pA[r]  = (const char*)g_A16 + (size_t)(M0 + row) * (KTOT * 2) + sl * 16;
        pB[r]  = (const char*)g_W16 + (size_t)(N0 + row) * (KTOT * 2) + sl * 16;
        sAo[r] = swz((uint32_t)row * 128, (uint32_t)sl * 16);
        sBo[r] = sAo[r];
    }

    auto issue_load = [&](int kc, int stage) {
        const uint32_t st = sbase + stage * G1_STG;
        const uint32_t cb = (uint32_t)kc * 128;
#pragma unroll
        for (int r = 0; r < 8; r++) {
            CP_ASYNC16(st + G1_A + sAo[r], pA[r] + cb);
            CP_ASYNC16(st + G1_B + sBo[r], pB[r] + cb);
        }
        CP_COMMIT();
    };

    // ---------- consumer addressing: warp (wm, wn) = 64x64 ----------
    const int wm = (wid & 1) * 64;
    const int wn = (wid >> 1) * 64;
    const uint32_t arow128 = (uint32_t)(wm + (lid & 15)) * 128;
    const uint32_t aq      = (uint32_t)((lid >> 4) * 16);
    const uint32_t brow128 = (uint32_t)(wn + (lid & 7) + ((lid >> 4) & 1) * 8) * 128;
    const uint32_t bq      = (uint32_t)(((lid >> 3) & 1) * 16);

    float acc[4][8][4];
#pragma unroll
    for (int i = 0; i < 4; i++)
#pragma unroll
        for (int j = 0; j < 8; j++)
#pragma unroll
            for (int q = 0; q < 4; q++) acc[i][j][q] = 0.f;

    issue_load(0, 0);
    issue_load(1, 1);

#pragma unroll 1
    for (int kc = 0; kc < G1_NC; kc++) {
        CP_WAIT1();
        __syncthreads();   // all warps done with chunk kc-1 -> slot (kc+2)%3 free
        if (kc + 2 < G1_NC) issue_load(kc + 2, (kc + 2) % 3);
        else CP_COMMIT();

        const uint32_t st = sbase + (kc % 3) * G1_STG;
#pragma unroll
        for (int kk = 0; kk < 4; kk++) {
            const uint32_t kb = (uint32_t)kk * 32;
            uint32_t A[4][4], B[4][4];
#pragma unroll
            for (int mt = 0; mt < 4; mt++)
                ldsm_x4(A[mt], st + G1_A + swz(arow128 + mt * 16 * 128, kb + aq));
#pragma unroll
            for (int nt = 0; nt < 4; nt++)
                ldsm_x4(B[nt], st + G1_B + swz(brow128 + nt * 16 * 128, kb + bq));
#pragma unroll
            for (int mt = 0; mt < 4; mt++)
#pragma unroll
                for (int nt = 0; nt < 4; nt++) {
                    mma_f16(acc[mt][2 * nt],     A[mt], B[nt][0], B[nt][1]);
                    mma_f16(acc[mt][2 * nt + 1], A[mt], B[nt][2], B[nt][3]);
                }
        }
    }

    // ---------- epilogue: bias + relu; fp32 h + bf16 hi/lo into g_A2bf ----------
#pragma unroll
    for (int mt = 0; mt < 4; mt++) {
        const int m = M0 + wm + mt * 16 + (lid >> 2);
#pragma unroll
        for (int nt = 0; nt < 8; nt++) {
            const int n = N0 + wn + nt * 8 + (lid & 3) * 2;
            const float2 bv = *(const float2*)(bh + n);
            float2 v0, v1;
            v0.x = acc[mt][nt][0] + bv.x; v0.y = acc[mt][nt][1] + bv.y;
            v1.x = acc[mt][nt][2] + bv.x; v1.y = acc[mt][nt][3] + bv.y;
            v0.x = v0.x > 0.f ? v0.x : 0.f; v0.y = v0.y > 0.f ? v0.y : 0.f;
            v1.x = v1.x > 0.f ? v1.x : 0.f; v1.y = v1.y > 0.f ? v1.y : 0.f;
            *(float2*)(hout + (size_t)m * HID + n)       = v0;
            *(float2*)(hout + (size_t)(m + 8) * HID + n) = v1;

            const __nv_bfloat16 h00 = __float2bfloat16_rn(v0.x);
            const __nv_bfloat16 h01 = __float2bfloat16_rn(v0.y);
            const __nv_bfloat16 h10 = __float2bfloat16_rn(v1.x);
            const __nv_bfloat16 h11 = __float2bfloat16_rn(v1.y);
            __nv_bfloat16* d0 = g_A2bf + (size_t)m * A2K + n;
            __nv_bfloat16* d1 = g_A2bf + (size_t)(m + 8) * A2K + n;
            *(__nv_bfloat162*)d0 = __nv_bfloat162(h00, h01);
            *(__nv_bfloat162*)d1 = __nv_bfloat162(h10, h11);
            *(__nv_bfloat162*)(d0 + HM) =
                __nv_bfloat162(__float2bfloat16_rn(v0.x - __bfloat162float(h00)),
                               __float2bfloat16_rn(v0.y - __bfloat162float(h01)));
            *(__nv_bfloat162*)(d1 + HM) =
                __nv_bfloat162(__float2bfloat16_rn(v1.x - __bfloat162float(h10)),
                               __float2bfloat16_rn(v1.y - __bfloat162float(h11)));
        }
    }
}

// ============================================================================
// GEMM2 via mma.sync + fused finish (proven round-5 version, unchanged).
// ============================================================================
#define NSTAGE 3
#define G2_TM 64
#define G2_NCHUNK 60
#define G2_SA (G2_TM * 128)
#define G2_SB (NUP * 128)
#define G2_STG (G2_SA + G2_SB)
#define G2_SMEM (3 * G2_STG)

__global__ __launch_bounds__(256, 1)
void gemm2_mma(const float* __restrict__ mem,
               const float* __restrict__ ba, const float* __restrict__ bb,
               const float* __restrict__ bva, const float* __restrict__ bvb,
               float* __restrict__ mem_new)
{
    extern __shared__ __align__(1024) unsigned char smem[];
    const uint32_t sbase = smem_u32(smem);
    const int tid = threadIdx.x;
    const int wid = tid >> 5;
    const int lid = tid & 31;
    const int M0 = blockIdx.x * G2_TM;

    const int prow = tid >> 3;
    const int pc   = tid & 7;
    const char* Ag = (const char*)g_A2bf + (size_t)(M0 + prow) * (A2K * 2) + pc * 16;
    const uint32_t sAoff = swz((uint32_t)prow * 128, (uint32_t)pc * 16);

    auto issue_load = [&](int kc, int stage) {
        uint32_t aoff, boff;
        if (kc < 20)      { aoff = kc * 128;               boff = kc * 128; }
        else if (kc < 40) { aoff = 2560 + (kc - 20) * 128; boff = (kc - 20) * 128; }
        else              { aoff = (kc - 40) * 128;        boff = 2560 + (kc - 40) * 128; }
        const uint32_t sa  = sbase + stage * G2_STG;
        const uint32_t sbB = sa + G2_SA;
#pragma unroll
        for (int r = 0; r < 2; r++)
            CP_ASYNC16(sa + sAoff + r * 4096, Ag + aoff + (size_t)r * (32 * A2K * 2));
#pragma unroll
        for (int r = 0; r < 5; r++) {
            const int idx = tid + 256 * r;
            if (idx < NUP * 8) {
                const int row = idx >> 3, c = idx & 7;
                CP_ASYNC16(sbB + swz((uint32_t)row * 128, (uint32_t)c * 16),
                           (const char*)g_W2bf + (size_t)row * (A2K * 2) + c * 16 + boff);
            }
        }
        CP_COMMIT();
    };

    const int wm = (wid & 3) * 16;
    const int wn = (wid >> 2) * 72;
    const uint32_t arow128 = (uint32_t)(wm + (lid & 15)) * 128;
    const uint32_t aq      = (uint32_t)((lid >> 4) * 16);
    const uint32_t brow128 = (uint32_t)((lid & 7) + ((lid >> 4) & 1) * 8) * 128;
    const uint32_t bq      = (uint32_t)(((lid >> 3) & 1) * 16);
    const uint32_t brow2   = (uint32_t)(lid & 7) * 128;

    float acc[9][4];
#pragma unroll
    for (int j = 0; j < 9; j++)
#pragma unroll
        for (int q = 0; q < 4; q++) acc[j][q] = 0.f;

    issue_load(0, 0);
    issue_load(1, 1);

#pragma unroll 1
    for (int kc = 0; kc < G2_NCHUNK; kc++) {
        CP_WAIT1();
        __syncthreads();
        if (kc + 2 < G2_NCHUNK) issue_load(kc + 2, (kc + 2) % NSTAGE);
        else CP_COMMIT();

        const uint32_t sa  = sbase + (kc % NSTAGE) * G2_STG;
        const uint32_t sbB = sa + G2_SA;
#pragma unroll
        for (int kk = 0; kk < 4; kk++) {
            const uint32_t kb = (uint32_t)kk * 32;
            uint32_t A[4];
            ldsm_x4(A, sa + swz(arow128, kb + aq));
            uint32_t Bf[4][4], Bt[2];
#pragma unroll
            for (int nt = 0; nt < 4; nt++)
                ldsm_x4(Bf[nt], sbB + swz(brow128 + (wn + nt * 16) * 128, kb + bq));
            ldsm_x2(Bt, sbB + swz(brow2 + (wn + 64) * 128, kb + bq));
#pragma unroll
            for (int nt = 0; nt < 4; nt++) {
                mma16816(acc[2 * nt],     A, Bf[nt][0], Bf[nt][1]);
                mma16816(acc[2 * nt + 1], A, Bf[nt][2], Bf[nt][3]);
            }
            mma16816(acc[8], A, Bt[0], Bt[1]);
        }
    }

    __syncthreads();
    float* su = (float*)smem;                      // [64][144]
    float* Pa = (float*)(smem + 64 * NUP * 4);     // [64][8]
    float* Pb = Pa + 64 * 8;
    {
        const int r0 = wm + (lid >> 2);
        const int r1 = r0 + 8;
#pragma unroll
        for (int nt = 0; nt < 9; nt++) {
            const int n = wn + nt * 8 + (lid & 3) * 2;
            float b0 = 0.f, b1 = 0.f;
            if (n < NU)     b0 = u_bias(n,     ba, bb, bva, bvb);
            if (n + 1 < NU) b1 = u_bias(n + 1, ba, bb, bva, bvb);
            su[r0 * NUP + n]     = acc[nt][0] + b0;
            su[r0 * NUP + n + 1] = acc[nt][1] + b1;
            su[r1 * NUP + n]     = acc[nt][2] + b0;
            su[r1 * NUP + n + 1] = acc[nt][3] + b1;
        }
    }
    __syncthreads();

    if (tid < 64) {
        const float* u   = su + tid * NUP;
        const float* al  = u;
        const float* be  = u + 4;
        const float* u0a = u + 8;
        const float* u1a = u + 40;
        const float* u0b = u + 72;
        const float* u1b = u + 104;

        float S1a = 0.f, S1b = 0.f;
#pragma unroll
        for (int j = 0; j < 32; j++) {
            const float xa = u1a[j], xa2 = xa * xa;
            const float xb = u1b[j], xb2 = xb * xb;
            S1a += xa2 * xa2 * fabsf(xa);
            S1b += xb2 * xb2 * fabsf(xb);
        }
        float ca[4], cb[4];
#pragma unroll
        for (int k = 0; k < 4; k++) {
            float S0a = 0.f, S0b = 0.f;
#pragma unroll
            for (int i = 0; i < 8; i++) {
                const float xa = u0a[8 * k + i], xa2 = xa * xa;
                const float xb = u0b[8 * k + i], xb2 = xb * xb;
                S0a += xa2 * xa2 * fabsf(xa);
                S0b += xb2 * xb2 * fabsf(xb);
            }
            const float na = fmaxf(exp2f(0.2f * log2f(S0a * S1a)), 1e-12f);
            const float nb = fmaxf(exp2f(0.2f * log2f(S0b * S1b)), 1e-12f);
            ca[k] = al[k] / na;
            cb[k] = be[k] / nb;
        }
#pragma unroll
        for (int ii = 0; ii < 8; ii++) {
            float pa = 0.f, pb = 0.f;
#pragma unroll
            for (int k = 0; k < 4; k++) {
                pa += ca[k] * u0a[8 * k + ii];
                pb += cb[k] * u0b[8 * k + ii];
            }
            Pa[tid * 8 + ii] = pa;
            Pb[tid * 8 + ii] = pb;
        }
    }
    __syncthreads();

#pragma unroll
    for (int e = 0; e < 64; e++) {
        const int idx = tid + e * 256;
        const int m = idx >> 8;
        const int c = idx & 255;
        const int ii = c >> 5;
        const int j  = c & 31;
        const float* u = su + m * NUP;
        mem_new[(size_t)(M0 + m) * MEMSZ + c] =
            mem[(size_t)(M0 + m) * MEMSZ + c] +
            0.25f * (u[40 + j] * Pa[m * 8 + ii] - u[104 + j] * Pb[m * 8 + ii]);
    }
}

// ============================================================================
// Launch
// ============================================================================
extern "C" void kernel_launch(void* const* d_in, const int* in_sizes, int n_in,
                              void* d_out, int out_size)
{
    const float* x   = (const float*)d_in[0];
    const float* h0  = (const float*)d_in[1];
    const float* mem = (const float*)d_in[2];
    const float* Wh  = (const float*)d_in[3];
    const float* bh  = (const float*)d_in[4];
    const float* Wa  = (const float*)d_in[5];
    const float* ba  = (const float*)d_in[6];
    const float* Wb  = (const float*)d_in[7];
    const float* bb  = (const float*)d_in[8];
    const float* Wva = (const float*)d_in[9];
    const float* bva = (const float*)d_in[10];
    const float* Wvb = (const float*)d_in[11];
    const float* bvb = (const float*)d_in[12];

    float* out     = (float*)d_out;
    float* mem_new = out;                              // [B, 256]
    float* h       = out + (size_t)B_ROWS * MEMSZ;     // [B, 1024]

    cudaFuncSetAttribute(gemm1_mma, cudaFuncAttributeMaxDynamicSharedMemorySize, G1_SMEM);
    cudaFuncSetAttribute(gemm2_mma, cudaFuncAttributeMaxDynamicSharedMemorySize, G2_SMEM);

    conv_all<<<NBLK_A + NBLK_W + NBLK_W2, 256>>>(x, h0, mem, Wh, Wa, Wb, Wva, Wvb);
    gemm1_mma<<<dim3(HID / G1_TN, B_ROWS / G1_TM), 128, G1_SMEM>>>(bh, h);
    gemm2_mma<<<B_ROWS / G2_TM, 256, G2_SMEM>>>(mem, ba, bb, bva, bvb, mem_new);
}

// round 10
// speedup vs baseline: 2.4225x; 1.0593x over previous
#include <cuda_runtime.h>
#include <cuda_bf16.h>
#include <cuda_fp16.h>
#include <cstdint>

#define B_ROWS 8192
#define INP    1024
#define HID    1024
#define MEMSZ  256
#define KTOT   2304   // INP + HID + MEMSZ
#define HM     1280   // HID + MEMSZ
#define A2K    2560   // hi|lo concat for gemm2 A
#define NU     136
#define NUP    144

// ------------------- device scratch (static: no allocation) -------------------
__device__ __align__(16) __half        g_A16[(size_t)B_ROWS * KTOT];   // A fp16 (rounded)
__device__ __align__(16) __half        g_W16[(size_t)HID * KTOT];      // W fp16 (rounded)
__device__ __align__(16) __nv_bfloat16 g_A2bf[(size_t)B_ROWS * A2K];   // gemm2 A hi|lo bf16
__device__ __align__(16) __nv_bfloat16 g_W2bf[(size_t)NUP * A2K];      // gemm2 W hi|lo bf16

// ============================ helpers ============================
__device__ __forceinline__ uint32_t smem_u32(const void* p) {
    uint32_t a;
    asm("{ .reg .u64 t; cvta.to.shared.u64 t, %1; cvt.u32.u64 %0, t; }" : "=r"(a) : "l"(p));
    return a;
}
__device__ __forceinline__ uint32_t swz(uint32_t rowbase128, uint32_t q) {
    return rowbase128 + (q ^ ((rowbase128 >> 3) & 0x70u));
}

#define CP_ASYNC16(saddr, gptr) \
    asm volatile("cp.async.cg.shared.global [%0], [%1], 16;" :: "r"(saddr), "l"(gptr))
#define CP_COMMIT() asm volatile("cp.async.commit_group;" ::: "memory")
#define CP_WAIT1()  asm volatile("cp.async.wait_group 1;" ::: "memory")

__device__ __forceinline__ void ldsm_x4(uint32_t* r, uint32_t addr) {
    asm volatile("ldmatrix.sync.aligned.m8n8.x4.shared.b16 {%0,%1,%2,%3}, [%4];"
                 : "=r"(r[0]), "=r"(r[1]), "=r"(r[2]), "=r"(r[3]) : "r"(addr));
}
__device__ __forceinline__ void ldsm_x2(uint32_t* r, uint32_t addr) {
    asm volatile("ldmatrix.sync.aligned.m8n8.x2.shared.b16 {%0,%1}, [%2];"
                 : "=r"(r[0]), "=r"(r[1]) : "r"(addr));
}
__device__ __forceinline__ void mma16816(float* d, const uint32_t* a,
                                         uint32_t b0, uint32_t b1) {
    asm volatile("mma.sync.aligned.m16n8k16.row.col.f32.bf16.bf16.f32 "
                 "{%0,%1,%2,%3}, {%4,%5,%6,%7}, {%8,%9}, {%0,%1,%2,%3};"
                 : "+f"(d[0]), "+f"(d[1]), "+f"(d[2]), "+f"(d[3])
                 : "r"(a[0]), "r"(a[1]), "r"(a[2]), "r"(a[3]), "r"(b0), "r"(b1));
}
__device__ __forceinline__ void mma_f16(float* d, const uint32_t* a,
                                        uint32_t b0, uint32_t b1) {
    asm volatile("mma.sync.aligned.m16n8k16.row.col.f32.f16.f16.f32 "
                 "{%0,%1,%2,%3}, {%4,%5,%6,%7}, {%8,%9}, {%0,%1,%2,%3};"
                 : "+f"(d[0]), "+f"(d[1]), "+f"(d[2]), "+f"(d[3])
                 : "r"(a[0]), "r"(a[1]), "r"(a[2]), "r"(a[3]), "r"(b0), "r"(b1));
}

// ============================================================================
// Fused conversion kernel (one launch): block ranges -> A, W, W2.
// ============================================================================
struct bf4 { __nv_bfloat162 a, b; };
struct hf4 { __half2 a, b; };

#define NBLK_A  (B_ROWS * (KTOT / 4) / 256)           // 18432
#define NBLK_W  (HID * (KTOT / 4) / 256)              // 2304
#define NBLK_W2 ((NUP * (HM / 4) + 255) / 256)        // 180

__device__ __forceinline__ const float* u_wrow(int n, const float* Wa, const float* Wb,
                                               const float* Wva, const float* Wvb)
{
    if (n < 4)  return Wa  + (size_t)n * HM;
    if (n < 8)  return Wb  + (size_t)(n - 4) * HM;
    if (n < 72) return Wva + (size_t)(n - 8) * HM;
    return Wvb + (size_t)(n - 72) * HM;
}
__device__ __forceinline__ float u_bias(int n, const float* ba, const float* bb,
                                        const float* bva, const float* bvb)
{
    if (n < 4)  return ba[n];
    if (n < 8)  return bb[n - 4];
    if (n < 72) return bva[n - 8];
    return bvb[n - 72];
}

__global__ void conv_all(const float* __restrict__ x, const float* __restrict__ h0,
                         const float* __restrict__ mem, const float* __restrict__ Wh,
                         const float* __restrict__ Wa, const float* __restrict__ Wb,
                         const float* __restrict__ Wva, const float* __restrict__ Wvb)
{
    const int blk = blockIdx.x;
    if (blk < NBLK_A) {
        // ---- A: fp32 -> fp16 (single rounding) ----
        const int gid = blk * 256 + threadIdx.x;
        const int row = gid / (KTOT / 4);
        const int k   = (gid % (KTOT / 4)) * 4;
        float4 v;
        if (k < INP)            v = *(const float4*)(x   + (size_t)row * INP + k);
        else if (k < INP + HID) v = *(const float4*)(h0  + (size_t)row * HID + (k - INP));
        else                    v = *(const float4*)(mem + (size_t)row * MEMSZ + (k - INP - HID));

        hf4 a16;
        a16.a = __half2(__float2half_rn(v.x), __float2half_rn(v.y));
        a16.b = __half2(__float2half_rn(v.z), __float2half_rn(v.w));
        *(hf4*)(g_A16 + (size_t)row * KTOT + k) = a16;

        if (k >= INP + HID) {   // memory slice feeds gemm2's A (cols 1024..1280)
            const int km = k - (INP + HID);
            const __nv_bfloat16 h0b = __float2bfloat16_rn(v.x);
            const __nv_bfloat16 h1b = __float2bfloat16_rn(v.y);
            const __nv_bfloat16 h2b = __float2bfloat16_rn(v.z);
            const __nv_bfloat16 h3b = __float2bfloat16_rn(v.w);
            bf4 bhi, blo;
            bhi.a = __nv_bfloat162(h0b, h1b);
            bhi.b = __nv_bfloat162(h2b, h3b);
            blo.a = __nv_bfloat162(__float2bfloat16_rn(v.x - __bfloat162float(h0b)),
                                   __float2bfloat16_rn(v.y - __bfloat162float(h1b)));
            blo.b = __nv_bfloat162(__float2bfloat16_rn(v.z - __bfloat162float(h2b)),
                                   __float2bfloat16_rn(v.w - __bfloat162float(h3b)));
            __nv_bfloat16* d = g_A2bf + (size_t)row * A2K + HID + km;
            *(bf4*)d        = bhi;
            *(bf4*)(d + HM) = blo;
        }
    } else if (blk < NBLK_A + NBLK_W) {
        // ---- W: fp32 -> fp16 single rounding ----
        const int gid = (blk - NBLK_A) * 256 + threadIdx.x;
        const int row = gid / (KTOT / 4);
        const int k   = (gid % (KTOT / 4)) * 4;
        const float4 v = *(const float4*)(Wh + (size_t)row * KTOT + k);
        hf4 w;
        w.a = __half2(__float2half_rn(v.x), __float2half_rn(v.y));
        w.b = __half2(__float2half_rn(v.z), __float2half_rn(v.w));
        *(hf4*)(g_W16 + (size_t)row * KTOT + k) = w;
    } else {
        // ---- W2: packed [144][1280] -> bf16 hi|lo ----
        const int gid = (blk - NBLK_A - NBLK_W) * 256 + threadIdx.x;
        if (gid >= NUP * (HM / 4)) return;
        const int n = gid / (HM / 4);
        const int k = (gid % (HM / 4)) * 4;
        float4 v = make_float4(0.f, 0.f, 0.f, 0.f);
        if (n < NU) v = *(const float4*)(u_wrow(n, Wa, Wb, Wva, Wvb) + k);
        const __nv_bfloat16 h0b = __float2bfloat16_rn(v.x);
        const __nv_bfloat16 h1b = __float2bfloat16_rn(v.y);
        const __nv_bfloat16 h2b = __float2bfloat16_rn(v.z);
        const __nv_bfloat16 h3b = __float2bfloat16_rn(v.w);
        bf4 hi, lo;
        hi.a = __nv_bfloat162(h0b, h1b);
        hi.b = __nv_bfloat162(h2b, h3b);
        lo.a = __nv_bfloat162(__float2bfloat16_rn(v.x - __bfloat162float(h0b)),
                              __float2bfloat16_rn(v.y - __bfloat162float(h1b)));
        lo.b = __nv_bfloat162(__float2bfloat16_rn(v.z - __bfloat162float(h2b)),
                              __float2bfloat16_rn(v.w - __bfloat162float(h3b)));
        __nv_bfloat16* dst = g_W2bf + (size_t)n * A2K + k;
        *(bf4*)dst        = hi;
        *(bf4*)(dst + HM) = lo;
    }
}

// ============================================================================
// GEMM1: pure fp16, single product. h = relu(A @ W^T + b).
// CTA 128x128, 128 threads (4 warps, each 64x64), 2 CTAs/SM.
// 3-stage smem pipeline + REGISTER double-buffered fragments (hide LDS lat).
// ============================================================================
#define G1_TM 128
#define G1_TN 128
#define G1_NC 36
#define G1_A   0
#define G1_B   16384
#define G1_STG 32768
#define G1_SMEM (3 * G1_STG)   // 98304

__global__ __launch_bounds__(128, 2)
void gemm1_mma(const float* __restrict__ bh, float* __restrict__ hout)
{
    extern __shared__ __align__(1024) unsigned char smem[];
    const uint32_t sbase = smem_u32(smem);
    const int tid = threadIdx.x;
    const int wid = tid >> 5;
    const int lid = tid & 31;
    const int N0 = blockIdx.x * G1_TN;
    const int M0 = blockIdx.y * G1_TM;

    // ---------- producer addressing ----------
    const char* pA[8];  uint32_t sAo[8];
    const char* pB[8];  uint32_t sBo[8];
#pragma unroll
    for (int r = 0; r < 8; r++) {
        const int idx = tid + 128 * r, row = idx >> 3, sl = idx & 7;
        pA[r]  = (const char*)g_A16 + (size_t)(M0 + row) * (KTOT * 2) + sl * 16;
        pB[r]  = (const char*)g_W16 + (size_t)(N0 + row) * (KTOT * 2) + sl * 16;
        sAo[r] = swz((uint32_t)row * 128, (uint32_t)sl * 16);
        sBo[r] = sAo[r];
    }

    auto issue_load = [&](int kc, int stage) {
        const uint32_t st = sbase + stage * G1_STG;
        const uint32_t cb = (uint32_t)kc * 128;
#pragma unroll
        for (int r = 0; r < 8; r++) {
            CP_ASYNC16(st + G1_A + sAo[r], pA[r] + cb);
            CP_ASYNC16(st + G1_B + sBo[r], pB[r] + cb);
        }
        CP_COMMIT();
    };

    // ---------- consumer addressing: warp 64x64 ----------
    const int wm = (wid & 1) * 64;
    const int wn = (wid >> 1) * 64;
    const uint32_t arow128 = (uint32_t)(wm + (lid & 15)) * 128;
    const uint32_t aq      = (uint32_t)((lid >> 4) * 16);
    const uint32_t brow128 = (uint32_t)(wn + (lid & 7) + ((lid >> 4) & 1) * 8) * 128;
    const uint32_t bq      = (uint32_t)(((lid >> 3) & 1) * 16);

    float acc[4][8][4];
#pragma unroll
    for (int i = 0; i < 4; i++)
#pragma unroll
        for (int j = 0; j < 8; j++)
#pragma unroll
            for (int q = 0; q < 4; q++) acc[i][j][q] = 0.f;

    issue_load(0, 0);
    issue_load(1, 1);

    uint32_t Af[2][4][4], Bf[2][4][4];   // double-buffered fragments

#pragma unroll 1
    for (int kc = 0; kc < G1_NC; kc++) {
        CP_WAIT1();
        __syncthreads();   // chunk kc resident; slot (kc+2)%3 free

        const uint32_t st = sbase + (kc % 3) * G1_STG;
        // prefetch kk=0 fragments FIRST (tensor pipe restarts sooner)
#pragma unroll
        for (int mt = 0; mt < 4; mt++)
            ldsm_x4(Af[0][mt], st + G1_A + swz(arow128 + mt * 16 * 128, aq));
#pragma unroll
        for (int nt = 0; nt < 4; nt++)
            ldsm_x4(Bf[0][nt], st + G1_B + swz(brow128 + nt * 16 * 128, bq));

        if (kc + 2 < G1_NC) issue_load(kc + 2, (kc + 2) % 3);
        else CP_COMMIT();

#pragma unroll
        for (int kk = 0; kk < 4; kk++) {
            const int cur = kk & 1, nxt = cur ^ 1;
            if (kk < 3) {   // prefetch kk+1 while computing kk
                const uint32_t kb = (uint32_t)(kk + 1) * 32;
#pragma unroll
                for (int mt = 0; mt < 4; mt++)
                    ldsm_x4(Af[nxt][mt], st + G1_A + swz(arow128 + mt * 16 * 128, kb + aq));
#pragma unroll
                for (int nt = 0; nt < 4; nt++)
                    ldsm_x4(Bf[nxt][nt], st + G1_B + swz(brow128 + nt * 16 * 128, kb + bq));
            }
#pragma unroll
            for (int mt = 0; mt < 4; mt++)
#pragma unroll
                for (int nt = 0; nt < 4; nt++) {
                    mma_f16(acc[mt][2 * nt],     Af[cur][mt], Bf[cur][nt][0], Bf[cur][nt][1]);
                    mma_f16(acc[mt][2 * nt + 1], Af[cur][mt], Bf[cur][nt][2], Bf[cur][nt][3]);
                }
        }
    }

    // ---------- epilogue: bias + relu; fp32 h + bf16 hi/lo into g_A2bf ----------
#pragma unroll
    for (int mt = 0; mt < 4; mt++) {
        const int m = M0 + wm + mt * 16 + (lid >> 2);
#pragma unroll
        for (int nt = 0; nt < 8; nt++) {
            const int n = N0 + wn + nt * 8 + (lid & 3) * 2;
            const float2 bv = *(const float2*)(bh + n);
            float2 v0, v1;
            v0.x = acc[mt][nt][0] + bv.x; v0.y = acc[mt][nt][1] + bv.y;
            v1.x = acc[mt][nt][2] + bv.x; v1.y = acc[mt][nt][3] + bv.y;
            v0.x = v0.x > 0.f ? v0.x : 0.f; v0.y = v0.y > 0.f ? v0.y : 0.f;
            v1.x = v1.x > 0.f ? v1.x : 0.f; v1.y = v1.y > 0.f ? v1.y : 0.f;
            *(float2*)(hout + (size_t)m * HID + n)       = v0;
            *(float2*)(hout + (size_t)(m + 8) * HID + n) = v1;

            const __nv_bfloat16 h00 = __float2bfloat16_rn(v0.x);
            const __nv_bfloat16 h01 = __float2bfloat16_rn(v0.y);
            const __nv_bfloat16 h10 = __float2bfloat16_rn(v1.x);
            const __nv_bfloat16 h11 = __float2bfloat16_rn(v1.y);
            __nv_bfloat16* d0 = g_A2bf + (size_t)m * A2K + n;
            __nv_bfloat16* d1 = g_A2bf + (size_t)(m + 8) * A2K + n;
            *(__nv_bfloat162*)d0 = __nv_bfloat162(h00, h01);
            *(__nv_bfloat162*)d1 = __nv_bfloat162(h10, h11);
            *(__nv_bfloat162*)(d0 + HM) =
                __nv_bfloat162(__float2bfloat16_rn(v0.x - __bfloat162float(h00)),
                               __float2bfloat16_rn(v0.y - __bfloat162float(h01)));
            *(__nv_bfloat162*)(d1 + HM) =
                __nv_bfloat162(__float2bfloat16_rn(v1.x - __bfloat162float(h10)),
                               __float2bfloat16_rn(v1.y - __bfloat162float(h11)));
        }
    }
}

// ============================================================================
// GEMM2 via mma.sync + fused finish (proven round-5 version, unchanged).
// ============================================================================
#define NSTAGE 3
#define G2_TM 64
#define G2_NCHUNK 60
#define G2_SA (G2_TM * 128)
#define G2_SB (NUP * 128)
#define G2_STG (G2_SA + G2_SB)
#define G2_SMEM (3 * G2_STG)

__global__ __launch_bounds__(256, 1)
void gemm2_mma(const float* __restrict__ mem,
               const float* __restrict__ ba, const float* __restrict__ bb,
               const float* __restrict__ bva, const float* __restrict__ bvb,
               float* __restrict__ mem_new)
{
    extern __shared__ __align__(1024) unsigned char smem[];
    const uint32_t sbase = smem_u32(smem);
    const int tid = threadIdx.x;
    const int wid = tid >> 5;
    const int lid = tid & 31;
    const int M0 = blockIdx.x * G2_TM;

    const int prow = tid >> 3;
    const int pc   = tid & 7;
    const char* Ag = (const char*)g_A2bf + (size_t)(M0 + prow) * (A2K * 2) + pc * 16;
    const uint32_t sAoff = swz((uint32_t)prow * 128, (uint32_t)pc * 16);

    auto issue_load = [&](int kc, int stage) {
        uint32_t aoff, boff;
        if (kc < 20)      { aoff = kc * 128;               boff = kc * 128; }
        else if (kc < 40) { aoff = 2560 + (kc - 20) * 128; boff = (kc - 20) * 128; }
        else              { aoff = (kc - 40) * 128;        boff = 2560 + (kc - 40) * 128; }
        const uint32_t sa  = sbase + stage * G2_STG;
        const uint32_t sbB = sa + G2_SA;
#pragma unroll
        for (int r = 0; r < 2; r++)
            CP_ASYNC16(sa + sAoff + r * 4096, Ag + aoff + (size_t)r * (32 * A2K * 2));
#pragma unroll
        for (int r = 0; r < 5; r++) {
            const int idx = tid + 256 * r;
            if (idx < NUP * 8) {
                const int row = idx >> 3, c = idx & 7;
                CP_ASYNC16(sbB + swz((uint32_t)row * 128, (uint32_t)c * 16),
                           (const char*)g_W2bf + (size_t)row * (A2K * 2) + c * 16 + boff);
            }
        }
        CP_COMMIT();
    };

    const int wm = (wid & 3) * 16;
    const int wn = (wid >> 2) * 72;
    const uint32_t arow128 = (uint32_t)(wm + (lid & 15)) * 128;
    const uint32_t aq      = (uint32_t)((lid >> 4) * 16);
    const uint32_t brow128 = (uint32_t)((lid & 7) + ((lid >> 4) & 1) * 8) * 128;
    const uint32_t bq      = (uint32_t)(((lid >> 3) & 1) * 16);
    const uint32_t brow2   = (uint32_t)(lid & 7) * 128;

    float acc[9][4];
#pragma unroll
    for (int j = 0; j < 9; j++)
#pragma unroll
        for (int q = 0; q < 4; q++) acc[j][q] = 0.f;

    issue_load(0, 0);
    issue_load(1, 1);

#pragma unroll 1
    for (int kc = 0; kc < G2_NCHUNK; kc++) {
        CP_WAIT1();
        __syncthreads();
        if (kc + 2 < G2_NCHUNK) issue_load(kc + 2, (kc + 2) % NSTAGE);
        else CP_COMMIT();

        const uint32_t sa  = sbase + (kc % NSTAGE) * G2_STG;
        const uint32_t sbB = sa + G2_SA;
#pragma unroll
        for (int kk = 0; kk < 4; kk++) {
            const uint32_t kb = (uint32_t)kk * 32;
            uint32_t A[4];
            ldsm_x4(A, sa + swz(arow128, kb + aq));
            uint32_t Bf[4][4], Bt[2];
#pragma unroll
            for (int nt = 0; nt < 4; nt++)
                ldsm_x4(Bf[nt], sbB + swz(brow128 + (wn + nt * 16) * 128, kb + bq));
            ldsm_x2(Bt, sbB + swz(brow2 + (wn + 64) * 128, kb + bq));
#pragma unroll
            for (int nt = 0; nt < 4; nt++) {
                mma16816(acc[2 * nt],     A, Bf[nt][0], Bf[nt][1]);
                mma16816(acc[2 * nt + 1], A, Bf[nt][2], Bf[nt][3]);
            }
            mma16816(acc[8], A, Bt[0], Bt[1]);
        }
    }

    __syncthreads();
    float* su = (float*)smem;                      // [64][144]
    float* Pa = (float*)(smem + 64 * NUP * 4);     // [64][8]
    float* Pb = Pa + 64 * 8;
    {
        const int r0 = wm + (lid >> 2);
        const int r1 = r0 + 8;
#pragma unroll
        for (int nt = 0; nt < 9; nt++) {
            const int n = wn + nt * 8 + (lid & 3) * 2;
            float b0 = 0.f, b1 = 0.f;
            if (n < NU)     b0 = u_bias(n,     ba, bb, bva, bvb);
            if (n + 1 < NU) b1 = u_bias(n + 1, ba, bb, bva, bvb);
            su[r0 * NUP + n]     = acc[nt][0] + b0;
            su[r0 * NUP + n + 1] = acc[nt][1] + b1;
            su[r1 * NUP + n]     = acc[nt][2] + b0;
            su[r1 * NUP + n + 1] = acc[nt][3] + b1;
        }
    }
    __syncthreads();

    if (tid < 64) {
        const float* u   = su + tid * NUP;
        const float* al  = u;
        const float* be  = u + 4;
        const float* u0a = u + 8;
        const float* u1a = u + 40;
        const float* u0b = u + 72;
        const float* u1b = u + 104;

        float S1a = 0.f, S1b = 0.f;
#pragma unroll
        for (int j = 0; j < 32; j++) {
            const float xa = u1a[j], xa2 = xa * xa;
            const float xb = u1b[j], xb2 = xb * xb;
            S1a += xa2 * xa2 * fabsf(xa);
            S1b += xb2 * xb2 * fabsf(xb);
        }
        float ca[4], cb[4];
#pragma unroll
        for (int k = 0; k < 4; k++) {
            float S0a = 0.f, S0b = 0.f;
#pragma unroll
            for (int i = 0; i < 8; i++) {
                const float xa = u0a[8 * k + i], xa2 = xa * xa;
                const float xb = u0b[8 * k + i], xb2 = xb * xb;
                S0a += xa2 * xa2 * fabsf(xa);
                S0b += xb2 * xb2 * fabsf(xb);
            }
            const float na = fmaxf(exp2f(0.2f * log2f(S0a * S1a)), 1e-12f);
            const float nb = fmaxf(exp2f(0.2f * log2f(S0b * S1b)), 1e-12f);
            ca[k] = al[k] / na;
            cb[k] = be[k] / nb;
        }
#pragma unroll
        for (int ii = 0; ii < 8; ii++) {
            float pa = 0.f, pb = 0.f;
#pragma unroll
            for (int k = 0; k < 4; k++) {
                pa += ca[k] * u0a[8 * k + ii];
                pb += cb[k] * u0b[8 * k + ii];
            }
            Pa[tid * 8 + ii] = pa;
            Pb[tid * 8 + ii] = pb;
        }
    }
    __syncthreads();

#pragma unroll
    for (int e = 0; e < 64; e++) {
        const int idx = tid + e * 256;
        const int m = idx >> 8;
        const int c = idx & 255;
        const int ii = c >> 5;
        const int j  = c & 31;
        const float* u = su + m * NUP;
        mem_new[(size_t)(M0 + m) * MEMSZ + c] =
            mem[(size_t)(M0 + m) * MEMSZ + c] +
            0.25f * (u[40 + j] * Pa[m * 8 + ii] - u[104 + j] * Pb[m * 8 + ii]);
    }
}

// ============================================================================
// Launch
// ============================================================================
extern "C" void kernel_launch(void* const* d_in, const int* in_sizes, int n_in,
                              void* d_out, int out_size)
{
    const float* x   = (const float*)d_in[0];
    const float* h0  = (const float*)d_in[1];
    const float* mem = (const float*)d_in[2];
    const float* Wh  = (const float*)d_in[3];
    const float* bh  = (const float*)d_in[4];
    const float* Wa  = (const float*)d_in[5];
    const float* ba  = (const float*)d_in[6];
    const float* Wb  = (const float*)d_in[7];
    const float* bb  = (const float*)d_in[8];
    const float* Wva = (const float*)d_in[9];
    const float* bva = (const float*)d_in[10];
    const float* Wvb = (const float*)d_in[11];
    const float* bvb = (const float*)d_in[12];

    float* out     = (float*)d_out;
    float* mem_new = out;                              // [B, 256]
    float* h       = out + (size_t)B_ROWS * MEMSZ;     // [B, 1024]

    cudaFuncSetAttribute(gemm1_mma, cudaFuncAttributeMaxDynamicSharedMemorySize, G1_SMEM);
    cudaFuncSetAttribute(gemm2_mma, cudaFuncAttributeMaxDynamicSharedMemorySize, G2_SMEM);

    conv_all<<<NBLK_A + NBLK_W + NBLK_W2, 256>>>(x, h0, mem, Wh, Wa, Wb, Wva, Wvb);
    gemm1_mma<<<dim3(HID / G1_TN, B_ROWS / G1_TM), 128, G1_SMEM>>>(bh, h);
    gemm2_mma<<<B_ROWS / G2_TM, 256, G2_SMEM>>>(mem, ba, bb, bva, bvb, mem_new);
}